// round 11
// baseline (speedup 1.0000x reference)
#include <cuda_runtime.h>
#include <cuda_bf16.h>
#include <cuda_fp16.h>
#include <math.h>
#include <stdint.h>

#define N_NODES 131072
#define N_EDGES 524288
#define N_GRAPHS 4096
#define D 256
#define EPS 1e-10f

// ---------------- scratch (device globals; no allocation allowed) ----------
__device__ float g_hx0[N_NODES * D];
__device__ float g_hx1[N_NODES * D];          // aliases x
__device__ __half g_h016[N_NODES * D];        // fp16 shadow of hx0 (GEMM A)
__device__ __half g_h116[N_NODES * D];        // fp16 shadow of hx1 (GEMM A)
__device__ __half g_e16[N_EDGES * D];         // bond features (fp16)
__device__ float g_agg[N_NODES * D];
__device__ __half g_t16[N_NODES * 2 * D];     // GIN hidden (fp16)
__device__ __half g_xconv16[N_NODES * D];     // GIN out (fp16, GEMM input only)
__device__ __half g_gi16[N_NODES * 3 * D];    // GRU gates (fp16)
__device__ __half g_gh16[N_NODES * 3 * D];
__device__ float g_g1[N_GRAPHS * 4 * D];
__device__ float g_g2[N_GRAPHS * 4 * D];
__device__ float g_hs[N_GRAPHS * D];
__device__ float g_cs[N_GRAPHS * D];
__device__ float g_qstar[N_GRAPHS * 2 * D];
__device__ float g_prod[N_NODES];
__device__ float g_m[N_GRAPHS];
__device__ float g_norm[N_GRAPHS];
__device__ float g_w1t[512 * 256];            // gin_w1^T  [N=512, K=256]
__device__ float g_w2t[256 * 512];            // gin_w2^T  [N=256, K=512]

// ---------------- helpers ----------------
__device__ __forceinline__ uint32_t smem_u32(const void* p) {
    uint32_t a;
    asm("{ .reg .u64 t; cvta.to.shared.u64 t, %1; cvt.u32.u64 %0, t; }" : "=r"(a) : "l"(p));
    return a;
}
__device__ __forceinline__ void atomicMaxFloat(float* addr, float val) {
    int* ia = (int*)addr;
    int cur = __float_as_int(*(volatile float*)addr);
    while (__int_as_float(cur) < val) {
        int old = atomicCAS(ia, cur, __float_as_int(val));
        if (old == cur) break;
        cur = old;
    }
}
__device__ __forceinline__ float sigmoidf_(float x) { return 1.0f / (1.0f + expf(-x)); }
__device__ __forceinline__ void mma_f16(float* c, const uint32_t* a, const uint32_t* b) {
    asm volatile(
        "mma.sync.aligned.m16n8k16.row.col.f32.f16.f16.f32 "
        "{%0,%1,%2,%3}, {%4,%5,%6,%7}, {%8,%9}, {%0,%1,%2,%3};"
        : "+f"(c[0]), "+f"(c[1]), "+f"(c[2]), "+f"(c[3])
        : "r"(a[0]), "r"(a[1]), "r"(a[2]), "r"(a[3]), "r"(b[0]), "r"(b[1]));
}
__device__ __forceinline__ void ldsm_x4(uint32_t* r, uint32_t saddr) {
    asm volatile("ldmatrix.sync.aligned.m8n8.x4.shared.b16 {%0,%1,%2,%3}, [%4];"
                 : "=r"(r[0]), "=r"(r[1]), "=r"(r[2]), "=r"(r[3]) : "r"(saddr));
}
__device__ __forceinline__ uint32_t pack_h2(float x, float y) {
    __half2 h = __float22half2_rn(make_float2(x, y));
    return *(uint32_t*)&h;
}
__device__ __forceinline__ void ld4h(const __half* p, float* o) {
    __half2 a = *(const __half2*)p;
    __half2 b = *(const __half2*)(p + 2);
    o[0] = __low2float(a); o[1] = __high2float(a);
    o[2] = __low2float(b); o[3] = __high2float(b);
}
__device__ __forceinline__ void st4h(__half* p, float4 v) {
    *(__half2*)p = __float22half2_rn(make_float2(v.x, v.y));
    *(__half2*)(p + 2) = __float22half2_rn(make_float2(v.z, v.w));
}

// ---------------- fp16 tensor-core GEMM: C[M,N] = A @ B^T + bias ----------
// A [M,K] row-major (fp32 or fp16), B [N,K] row-major fp32,
// C [M,N] (fp32 or fp16). M%128==0, N%256==0, K%32==0.
// Block 128x256, BK=32, 16 warps (2m x 8n), warp tile 64x32.
static constexpr int GEMM_RSTRIDE_B = 80;
static constexpr int GEMM_A_BYTES = 128 * GEMM_RSTRIDE_B;
static constexpr int GEMM_B_BYTES = 256 * GEMM_RSTRIDE_B;
static constexpr int GEMM_BUF_BYTES = GEMM_A_BYTES + GEMM_B_BYTES;
static constexpr int GEMM_SMEM = 2 * GEMM_BUF_BYTES;
static constexpr int GEMM_TPB = 512;

template <bool RELU, bool AH, bool CH>
__global__ __launch_bounds__(GEMM_TPB, 1) void mma_gemm_kernel(
    const void* __restrict__ A_, const float* __restrict__ B,
    const float* __restrict__ bias, void* __restrict__ C_,
    int M, int N, int K) {
    extern __shared__ char smc[];
    const int tid = threadIdx.x;
    const int lane = tid & 31;
    const int warp = tid >> 5;
    const int wm = warp & 1;
    const int wn = warp >> 1;
    const int m0 = blockIdx.y * 128;
    const int n0 = blockIdx.x * 256;
    const uint32_t sbase = smem_u32(smc);
    const int ar = tid >> 3, ac = tid & 7;
    const int g = lane >> 3, r8 = lane & 7;
    const uint32_t a_l = (uint32_t)((wm * 64 + (g & 1) * 8 + r8) * GEMM_RSTRIDE_B +
                                    (g >> 1) * 16);
    const uint32_t b_l = (uint32_t)((wn * 32 + (g & 1) * 8 + r8) * GEMM_RSTRIDE_B +
                                    (g >> 1) * 16) + GEMM_A_BYTES;

    float acc[4][4][4];
#pragma unroll
    for (int i = 0; i < 4; i++)
#pragma unroll
        for (int j = 0; j < 4; j++)
#pragma unroll
            for (int q = 0; q < 4; q++) acc[i][j][q] = 0.f;

    const int niter = K >> 5;
    float4 pa[2], pb[4];
    uint2 pa16[2];

#define LDG_TILE(k0i)                                                              \
    do {                                                                           \
        const float* Bg = B + (size_t)n0 * K + (k0i) * 32;                         \
        if (AH) {                                                                  \
            const __half* Ag = (const __half*)A_ + (size_t)m0 * K + (k0i) * 32;    \
            _Pragma("unroll")                                                      \
            for (int i = 0; i < 2; i++)                                            \
                pa16[i] = *(const uint2*)&Ag[(size_t)(ar + i * 64) * K + ac * 4];  \
        } else {                                                                   \
            const float* Ag = (const float*)A_ + (size_t)m0 * K + (k0i) * 32;      \
            _Pragma("unroll")                                                      \
            for (int i = 0; i < 2; i++)                                            \
                pa[i] = *(const float4*)&Ag[(size_t)(ar + i * 64) * K + ac * 4];   \
        }                                                                          \
        _Pragma("unroll")                                                          \
        for (int i = 0; i < 4; i++)                                                \
            pb[i] = *(const float4*)&Bg[(size_t)(ar + i * 64) * K + ac * 4];       \
    } while (0)

#define STS_TILE(buf)                                                              \
    do {                                                                           \
        char* Ab_ = smc + (buf) * GEMM_BUF_BYTES;                                  \
        char* Bb_ = Ab_ + GEMM_A_BYTES;                                            \
        _Pragma("unroll")                                                          \
        for (int i = 0; i < 2; i++) {                                              \
            uint2* p = (uint2*)(Ab_ + (ar + i * 64) * GEMM_RSTRIDE_B + ac * 8);    \
            if (AH) *p = pa16[i];                                                  \
            else                                                                   \
                *p = make_uint2(pack_h2(pa[i].x, pa[i].y),                         \
                                pack_h2(pa[i].z, pa[i].w));                        \
        }                                                                          \
        _Pragma("unroll")                                                          \
        for (int i = 0; i < 4; i++) {                                              \
            uint2* p = (uint2*)(Bb_ + (ar + i * 64) * GEMM_RSTRIDE_B + ac * 8);    \
            *p = make_uint2(pack_h2(pb[i].x, pb[i].y), pack_h2(pb[i].z, pb[i].w)); \
        }                                                                          \
    } while (0)

    LDG_TILE(0);
    STS_TILE(0);
    __syncthreads();
    if (niter > 1) LDG_TILE(1);

    for (int k0i = 0; k0i < niter; k0i++) {
        if (k0i + 1 < niter) STS_TILE((k0i + 1) & 1);
        if (k0i + 2 < niter) LDG_TILE(k0i + 2);

        const uint32_t base = sbase + (uint32_t)((k0i & 1) * GEMM_BUF_BYTES);
        const uint32_t aaddr = base + a_l;
        const uint32_t baddr = base + b_l;
#pragma unroll
        for (int ks = 0; ks < 2; ks++) {
            uint32_t a[4][4];
#pragma unroll
            for (int i = 0; i < 4; i++)
                ldsm_x4(a[i], aaddr + (uint32_t)(i * 16 * GEMM_RSTRIDE_B + ks * 32));
            uint32_t b[4][2];
#pragma unroll
            for (int jj = 0; jj < 2; jj++) {
                uint32_t t[4];
                ldsm_x4(t, baddr + (uint32_t)(jj * 16 * GEMM_RSTRIDE_B + ks * 32));
                b[2 * jj][0] = t[0]; b[2 * jj][1] = t[2];
                b[2 * jj + 1][0] = t[1]; b[2 * jj + 1][1] = t[3];
            }
#pragma unroll
            for (int i = 0; i < 4; i++)
#pragma unroll
                for (int j = 0; j < 4; j++) mma_f16(acc[i][j], a[i], b[j]);
        }
        __syncthreads();
    }

#pragma unroll
    for (int i = 0; i < 4; i++) {
        int mr = m0 + wm * 64 + i * 16 + (lane >> 2);
#pragma unroll
        for (int j = 0; j < 4; j++) {
            int nc = n0 + wn * 32 + j * 8 + (lane & 3) * 2;
            float b0 = bias[nc], b1 = bias[nc + 1];
            float v0 = acc[i][j][0] + b0;
            float v1 = acc[i][j][1] + b1;
            float v2 = acc[i][j][2] + b0;
            float v3 = acc[i][j][3] + b1;
            if (RELU) {
                v0 = fmaxf(v0, 0.f); v1 = fmaxf(v1, 0.f);
                v2 = fmaxf(v2, 0.f); v3 = fmaxf(v3, 0.f);
            }
            if (CH) {
                __half* C = (__half*)C_;
                *(__half2*)&C[(size_t)mr * N + nc] =
                    __float22half2_rn(make_float2(v0, v1));
                *(__half2*)&C[(size_t)(mr + 8) * N + nc] =
                    __float22half2_rn(make_float2(v2, v3));
            } else {
                float* C = (float*)C_;
                *(float2*)&C[(size_t)mr * N + nc] = make_float2(v0, v1);
                *(float2*)&C[(size_t)(mr + 8) * N + nc] = make_float2(v2, v3);
            }
        }
    }
#undef LDG_TILE
#undef STS_TILE
}

// ---------------- weight transpose (tiny, once per launch) ----------------
__global__ void transpose_kernel(const float* __restrict__ in, float* __restrict__ out,
                                 int R, int C) {
    __shared__ float t[32][33];
    int c0 = blockIdx.x * 32, r0 = blockIdx.y * 32;
    for (int i = threadIdx.y; i < 32; i += 8)
        t[i][threadIdx.x] = in[(size_t)(r0 + i) * C + c0 + threadIdx.x];
    __syncthreads();
    for (int i = threadIdx.y; i < 32; i += 8)
        out[(size_t)(c0 + i) * R + r0 + threadIdx.x] = t[threadIdx.x][i];
}

// ---------------- encoders ----------------
__global__ void atom_encode_kernel(const int* __restrict__ xa,
                                   const float* __restrict__ emb,
                                   float* __restrict__ hx0, float* __restrict__ hx1,
                                   float* __restrict__ agg,
                                   __half* __restrict__ h016,
                                   __half* __restrict__ h116) {
    size_t idx = (size_t)blockIdx.x * blockDim.x + threadIdx.x;
    if (idx >= (size_t)N_NODES * 64) return;
    int n = (int)(idx >> 6);
    int c = (int)(idx & 63);
    float4 acc = make_float4(0.f, 0.f, 0.f, 0.f);
#pragma unroll
    for (int i = 0; i < 9; i++) {
        int t = xa[n * 9 + i];
        const float4 v = *(const float4*)&emb[((size_t)(i * 120 + t)) * D + c * 4];
        acc.x += v.x; acc.y += v.y; acc.z += v.z; acc.w += v.w;
    }
    size_t o = (size_t)n * D + c * 4;
    *(float4*)&hx0[o] = acc;
    *(float4*)&hx1[o] = acc;
    *(float4*)&agg[o] = acc;
    st4h(h016 + o, acc);
    st4h(h116 + o, acc);
}

// bond table (18KB) cached in smem; grid-stride over edges; fp16 output
__global__ void bond_encode_kernel(const int* __restrict__ ea,
                                   const float* __restrict__ emb,
                                   __half* __restrict__ e_out) {
    __shared__ float tab[3 * 6 * D];
    for (int i = threadIdx.x; i < 3 * 6 * D; i += blockDim.x) tab[i] = emb[i];
    __syncthreads();
    size_t total = (size_t)N_EDGES * 64;
    size_t stride = (size_t)gridDim.x * blockDim.x;
    for (size_t idx = (size_t)blockIdx.x * blockDim.x + threadIdx.x; idx < total;
         idx += stride) {
        int n = (int)(idx >> 6);
        int c = (int)(idx & 63);
        float4 acc = make_float4(0.f, 0.f, 0.f, 0.f);
#pragma unroll
        for (int i = 0; i < 3; i++) {
            int t = ea[n * 3 + i];
            const float4 v = *(const float4*)&tab[(i * 6 + t) * D + c * 4];
            acc.x += v.x; acc.y += v.y; acc.z += v.z; acc.w += v.w;
        }
        st4h(e_out + (size_t)n * D + c * 4, acc);
    }
}

// ---------------- edge scatter ----------------
__global__ void edge_scatter_kernel(const int* __restrict__ ei,
                                    const float* __restrict__ x,
                                    const __half* __restrict__ e,
                                    float* __restrict__ agg) {
    size_t idx = (size_t)blockIdx.x * blockDim.x + threadIdx.x;
    if (idx >= (size_t)N_EDGES * 64) return;
    int ed = (int)(idx >> 6);
    int c = (int)(idx & 63);
    int s = ei[ed];
    int d = ei[N_EDGES + ed];
    float4 xv = *(const float4*)&x[(size_t)s * D + c * 4];
    float ev[4];
    ld4h(e + (size_t)ed * D + c * 4, ev);
    float4 m;
    m.x = fmaxf(xv.x + ev[0], 0.f);
    m.y = fmaxf(xv.y + ev[1], 0.f);
    m.z = fmaxf(xv.z + ev[2], 0.f);
    m.w = fmaxf(xv.w + ev[3], 0.f);
    atomicAdd((float4*)&agg[(size_t)d * D + c * 4], m);
}

// ---------------- GRU / LSTM gates ----------------
__global__ void gru_gate_kernel(const __half* __restrict__ gi,
                                const __half* __restrict__ gh,
                                float* __restrict__ hx,
                                __half* __restrict__ h16_out,
                                float* __restrict__ agg_out) {
    size_t idx = (size_t)blockIdx.x * blockDim.x + threadIdx.x;
    if (idx >= (size_t)N_NODES * 64) return;
    int n = (int)(idx >> 6);
    int c = (int)(idx & 63);
    size_t base = (size_t)n * 3 * D + c * 4;
    float ir[4], iz[4], in_[4], hr[4], hz[4], hn[4];
    ld4h(gi + base, ir); ld4h(gi + base + D, iz); ld4h(gi + base + 2 * D, in_);
    ld4h(gh + base, hr); ld4h(gh + base + D, hz); ld4h(gh + base + 2 * D, hn);
    size_t hidx = (size_t)n * D + c * 4;
    float4 hp = *(const float4*)&hx[hidx];
    float hpv[4] = {hp.x, hp.y, hp.z, hp.w};
    float ov[4];
#pragma unroll
    for (int q = 0; q < 4; q++) {
        float r = sigmoidf_(ir[q] + hr[q]);
        float z = sigmoidf_(iz[q] + hz[q]);
        float nn = tanhf(in_[q] + r * hn[q]);
        ov[q] = (1.0f - z) * nn + z * hpv[q];
    }
    float4 o = make_float4(ov[0], ov[1], ov[2], ov[3]);
    *(float4*)&hx[hidx] = o;
    st4h(h16_out + hidx, o);
    if (agg_out) *(float4*)&agg_out[hidx] = o;
}

__global__ void lstm_gate_kernel(const float* __restrict__ g1,
                                 const float* __restrict__ g2,
                                 float* __restrict__ hs, float* __restrict__ cs) {
    size_t idx = (size_t)blockIdx.x * blockDim.x + threadIdx.x;
    if (idx >= (size_t)N_GRAPHS * D) return;
    int b = (int)(idx >> 8);
    int d = (int)(idx & 255);
    size_t base = (size_t)b * 4 * D + d;
    float ig = sigmoidf_(g1[base] + g2[base]);
    float fg = sigmoidf_(g1[base + D] + g2[base + D]);
    float gg = tanhf(g1[base + 2 * D] + g2[base + 2 * D]);
    float og = sigmoidf_(g1[base + 3 * D] + g2[base + 3 * D]);
    float c = fg * cs[idx] + ig * gg;
    cs[idx] = c;
    hs[idx] = og * tanhf(c);
}

// ---------------- Set2Set attention ----------------
__global__ void s2s_prep_kernel(float* __restrict__ qstar,
                                const float* __restrict__ hs,
                                float* __restrict__ m, float* __restrict__ norm) {
    size_t i = (size_t)blockIdx.x * blockDim.x + threadIdx.x;
    if (i < N_GRAPHS) { m[i] = -INFINITY; norm[i] = 0.f; }
    if (i < (size_t)N_GRAPHS * D) {
        int b = (int)(i >> 8);
        int d = (int)(i & 255);
        qstar[(size_t)b * 2 * D + d] = hs[i];
        qstar[(size_t)b * 2 * D + D + d] = 0.f;
    }
}

__global__ void attn_prod_kernel(const float* __restrict__ hs,
                                 const float* __restrict__ x,
                                 const int* __restrict__ batch,
                                 float* __restrict__ prod) {
    int warp = (int)(((size_t)blockIdx.x * blockDim.x + threadIdx.x) >> 5);
    int lane = threadIdx.x & 31;
    if (warp >= N_NODES) return;
    int b = batch[warp];
    const float* q = hs + (size_t)b * D;
    const float* xv = x + (size_t)warp * D;
    float s = 0.f;
#pragma unroll
    for (int j = 0; j < D / 32; j++) s += q[lane + j * 32] * xv[lane + j * 32];
#pragma unroll
    for (int o = 16; o; o >>= 1) s += __shfl_xor_sync(0xFFFFFFFFu, s, o);
    if (lane == 0) prod[warp] = s;
}

__global__ void attn_max_kernel(const int* __restrict__ batch,
                                const float* __restrict__ prod,
                                float* __restrict__ m) {
    int n = (int)((size_t)blockIdx.x * blockDim.x + threadIdx.x);
    if (n >= N_NODES) return;
    atomicMaxFloat(&m[batch[n]], prod[n]);
}

__global__ void attn_expnorm_kernel(const int* __restrict__ batch,
                                    float* __restrict__ prod,
                                    const float* __restrict__ m,
                                    float* __restrict__ norm) {
    int n = (int)((size_t)blockIdx.x * blockDim.x + threadIdx.x);
    if (n >= N_NODES) return;
    int b = batch[n];
    float a = expf(prod[n] - m[b]);
    prod[n] = a;
    atomicAdd(&norm[b], a);
}

__global__ void attn_scatter_kernel(const int* __restrict__ batch,
                                    const float* __restrict__ prod,
                                    const float* __restrict__ norm,
                                    const float* __restrict__ x,
                                    float* __restrict__ qstar) {
    size_t idx = (size_t)blockIdx.x * blockDim.x + threadIdx.x;
    if (idx >= (size_t)N_NODES * 64) return;
    int n = (int)(idx >> 6);
    int c = (int)(idx & 63);
    int b = batch[n];
    float coef = prod[n] / (norm[b] + EPS);
    float4 xv = *(const float4*)&x[(size_t)n * D + c * 4];
    float4 v = make_float4(coef * xv.x, coef * xv.y, coef * xv.z, coef * xv.w);
    atomicAdd((float4*)&qstar[(size_t)b * 2 * D + D + c * 4], v);
}

__global__ void fc_kernel(const float* __restrict__ qstar,
                          const float* __restrict__ fw,
                          const float* __restrict__ fb,
                          float* __restrict__ out) {
    int warp = (int)(((size_t)blockIdx.x * blockDim.x + threadIdx.x) >> 5);
    int lane = threadIdx.x & 31;
    if (warp >= N_GRAPHS) return;
    float s = 0.f;
#pragma unroll
    for (int j = 0; j < (2 * D) / 32; j++)
        s += qstar[(size_t)warp * 2 * D + lane + j * 32] * fw[lane + j * 32];
#pragma unroll
    for (int o = 16; o; o >>= 1) s += __shfl_xor_sync(0xFFFFFFFFu, s, o);
    if (lane == 0) out[warp] = s + fb[0];
}

// ---------------- launch ----------------
extern "C" void kernel_launch(void* const* d_in, const int* in_sizes, int n_in,
                              void* d_out, int out_size) {
    const int* x_atoms = (const int*)d_in[0];
    const int* edge_index = (const int*)d_in[1];
    const int* edge_attr = (const int*)d_in[2];
    const int* batch = (const int*)d_in[3];
    const float* atom_emb = (const float*)d_in[4];
    const float* bond_emb = (const float*)d_in[5];
    const float* gin_w1 = (const float*)d_in[6];
    const float* gin_b1 = (const float*)d_in[7];
    const float* gin_w2 = (const float*)d_in[8];
    const float* gin_b2 = (const float*)d_in[9];
    const float* gru_wih = (const float*)d_in[10];
    const float* gru_whh = (const float*)d_in[11];
    const float* gru_bih = (const float*)d_in[12];
    const float* gru_bhh = (const float*)d_in[13];
    const float* lstm_wih = (const float*)d_in[14];
    const float* lstm_whh = (const float*)d_in[15];
    const float* lstm_bih = (const float*)d_in[16];
    const float* lstm_bhh = (const float*)d_in[17];
    const float* fc_w = (const float*)d_in[18];
    const float* fc_b = (const float*)d_in[19];
    float* out = (float*)d_out;

    float *hx0, *hx1, *agg, *g1, *g2, *hs, *cs, *qstar, *prod, *mbuf, *norm,
        *w1t, *w2t;
    __half *h016, *h116, *e16, *t16, *xconv16, *gi16, *gh16;
    cudaGetSymbolAddress((void**)&hx0, g_hx0);
    cudaGetSymbolAddress((void**)&hx1, g_hx1);
    cudaGetSymbolAddress((void**)&h016, g_h016);
    cudaGetSymbolAddress((void**)&h116, g_h116);
    cudaGetSymbolAddress((void**)&e16, g_e16);
    cudaGetSymbolAddress((void**)&agg, g_agg);
    cudaGetSymbolAddress((void**)&t16, g_t16);
    cudaGetSymbolAddress((void**)&xconv16, g_xconv16);
    cudaGetSymbolAddress((void**)&gi16, g_gi16);
    cudaGetSymbolAddress((void**)&gh16, g_gh16);
    cudaGetSymbolAddress((void**)&g1, g_g1);
    cudaGetSymbolAddress((void**)&g2, g_g2);
    cudaGetSymbolAddress((void**)&hs, g_hs);
    cudaGetSymbolAddress((void**)&cs, g_cs);
    cudaGetSymbolAddress((void**)&qstar, g_qstar);
    cudaGetSymbolAddress((void**)&prod, g_prod);
    cudaGetSymbolAddress((void**)&mbuf, g_m);
    cudaGetSymbolAddress((void**)&norm, g_norm);
    cudaGetSymbolAddress((void**)&w1t, g_w1t);
    cudaGetSymbolAddress((void**)&w2t, g_w2t);

    cudaFuncSetAttribute(mma_gemm_kernel<true, false, true>,
                         cudaFuncAttributeMaxDynamicSharedMemorySize, GEMM_SMEM);
    cudaFuncSetAttribute(mma_gemm_kernel<false, true, true>,
                         cudaFuncAttributeMaxDynamicSharedMemorySize, GEMM_SMEM);
    cudaFuncSetAttribute(mma_gemm_kernel<false, false, false>,
                         cudaFuncAttributeMaxDynamicSharedMemorySize, GEMM_SMEM);

    const int TPB = 256;

    transpose_kernel<<<dim3(512 / 32, 256 / 32), dim3(32, 8)>>>(gin_w1, w1t, 256, 512);
    transpose_kernel<<<dim3(256 / 32, 512 / 32), dim3(32, 8)>>>(gin_w2, w2t, 512, 256);

    atom_encode_kernel<<<(N_NODES * 64) / TPB, TPB>>>(x_atoms, atom_emb, hx0, hx1, agg,
                                                      h016, h116);
    bond_encode_kernel<<<2048, TPB>>>(edge_attr, bond_emb, e16);
    cudaMemsetAsync(hs, 0, (size_t)N_GRAPHS * D * sizeof(float));
    cudaMemsetAsync(cs, 0, (size_t)N_GRAPHS * D * sizeof(float));
    cudaMemsetAsync(qstar, 0, (size_t)N_GRAPHS * 2 * D * sizeof(float));

    for (int layer = 0; layer < 3; layer++) {
        edge_scatter_kernel<<<(N_EDGES * 64) / TPB, TPB>>>(edge_index, hx1, e16, agg);
        // GIN MLP: agg(fp32) -> t16 -> xconv16
        mma_gemm_kernel<true, false, true>
            <<<dim3(512 / 256, N_NODES / 128), GEMM_TPB, GEMM_SMEM>>>(
                agg, w1t, gin_b1, t16, N_NODES, 512, 256);
        mma_gemm_kernel<false, true, true>
            <<<dim3(256 / 256, N_NODES / 128), GEMM_TPB, GEMM_SMEM>>>(
                t16, w2t, gin_b2, xconv16, N_NODES, 256, 512);
        // GRU layer 0: gi = xconv16 @ Wi^T, gh = h016 @ Wh^T
        mma_gemm_kernel<false, true, true>
            <<<dim3(768 / 256, N_NODES / 128), GEMM_TPB, GEMM_SMEM>>>(
                xconv16, gru_wih, gru_bih, gi16, N_NODES, 768, 256);
        mma_gemm_kernel<false, true, true>
            <<<dim3(768 / 256, N_NODES / 128), GEMM_TPB, GEMM_SMEM>>>(
                h016, gru_whh, gru_bhh, gh16, N_NODES, 768, 256);
        gru_gate_kernel<<<(N_NODES * 64) / TPB, TPB>>>(gi16, gh16, hx0, h016,
                                                       (float*)nullptr);
        // GRU layer 1: gi = h016 @ Wi^T, gh = h116 @ Wh^T
        mma_gemm_kernel<false, true, true>
            <<<dim3(768 / 256, N_NODES / 128), GEMM_TPB, GEMM_SMEM>>>(
                h016, gru_wih + 768 * 256, gru_bih + 768, gi16, N_NODES, 768, 256);
        mma_gemm_kernel<false, true, true>
            <<<dim3(768 / 256, N_NODES / 128), GEMM_TPB, GEMM_SMEM>>>(
                h116, gru_whh + 768 * 256, gru_bhh + 768, gh16, N_NODES, 768, 256);
        gru_gate_kernel<<<(N_NODES * 64) / TPB, TPB>>>(
            gi16, gh16, hx1, h116, layer < 2 ? agg : (float*)nullptr);
    }

    for (int step = 0; step < 3; step++) {
        mma_gemm_kernel<false, false, false>
            <<<dim3(1024 / 256, N_GRAPHS / 128), GEMM_TPB, GEMM_SMEM>>>(
                qstar, lstm_wih, lstm_bih, g1, N_GRAPHS, 1024, 512);
        mma_gemm_kernel<false, false, false>
            <<<dim3(1024 / 256, N_GRAPHS / 128), GEMM_TPB, GEMM_SMEM>>>(
                hs, lstm_whh, lstm_bhh, g2, N_GRAPHS, 1024, 256);
        lstm_gate_kernel<<<(N_GRAPHS * D) / TPB, TPB>>>(g1, g2, hs, cs);
        s2s_prep_kernel<<<(N_GRAPHS * D) / TPB, TPB>>>(qstar, hs, mbuf, norm);
        attn_prod_kernel<<<(N_NODES * 32) / TPB, TPB>>>(hs, hx1, batch, prod);
        attn_max_kernel<<<N_NODES / TPB, TPB>>>(batch, prod, mbuf);
        attn_expnorm_kernel<<<N_NODES / TPB, TPB>>>(batch, prod, mbuf, norm);
        attn_scatter_kernel<<<(N_NODES * 64) / TPB, TPB>>>(batch, prod, norm, hx1, qstar);
    }

    fc_kernel<<<(N_GRAPHS * 32) / TPB, TPB>>>(qstar, fc_w, fc_b, out);
}

// round 12
// speedup vs baseline: 1.0326x; 1.0326x over previous
#include <cuda_runtime.h>
#include <cuda_bf16.h>
#include <cuda_fp16.h>
#include <math.h>
#include <stdint.h>

#define N_NODES 131072
#define N_EDGES 524288
#define N_GRAPHS 4096
#define D 256
#define EPS 1e-10f

// ---------------- scratch (device globals; no allocation allowed) ----------
__device__ float g_hx0[N_NODES * D];
__device__ float g_hx1[N_NODES * D];          // aliases x
__device__ __half g_e16[N_EDGES * D];         // bond features (fp16)
__device__ float g_agg[N_NODES * D];
__device__ __half g_t16[N_NODES * 2 * D];
__device__ __half g_xconv16[N_NODES * D];
__device__ __half g_gi16[N_NODES * 3 * D];
__device__ __half g_gh16[N_NODES * 3 * D];
__device__ float g_g1[N_GRAPHS * 4 * D];
__device__ float g_g2[N_GRAPHS * 4 * D];
__device__ float g_hs[N_GRAPHS * D];
__device__ float g_cs[N_GRAPHS * D];
__device__ float g_qstar[N_GRAPHS * 2 * D];
__device__ float g_prod[N_NODES];
__device__ float g_m[N_GRAPHS];
__device__ float g_norm[N_GRAPHS];
__device__ float g_w1t[512 * 256];
__device__ float g_w2t[256 * 512];
// CSR (built once per call)
__device__ int g_count[N_NODES];
__device__ int g_rowstart[N_NODES + 1];
__device__ int g_cursor[N_NODES];
__device__ int g_csr_src[N_EDGES];
__device__ int g_csr_eid[N_EDGES];

// ---------------- helpers ----------------
__device__ __forceinline__ uint32_t smem_u32(const void* p) {
    uint32_t a;
    asm("{ .reg .u64 t; cvta.to.shared.u64 t, %1; cvt.u32.u64 %0, t; }" : "=r"(a) : "l"(p));
    return a;
}
__device__ __forceinline__ void atomicMaxFloat(float* addr, float val) {
    int* ia = (int*)addr;
    int cur = __float_as_int(*(volatile float*)addr);
    while (__int_as_float(cur) < val) {
        int old = atomicCAS(ia, cur, __float_as_int(val));
        if (old == cur) break;
        cur = old;
    }
}
__device__ __forceinline__ float sigmoidf_(float x) { return 1.0f / (1.0f + expf(-x)); }
__device__ __forceinline__ void mma_f16(float* c, const uint32_t* a, const uint32_t* b) {
    asm volatile(
        "mma.sync.aligned.m16n8k16.row.col.f32.f16.f16.f32 "
        "{%0,%1,%2,%3}, {%4,%5,%6,%7}, {%8,%9}, {%0,%1,%2,%3};"
        : "+f"(c[0]), "+f"(c[1]), "+f"(c[2]), "+f"(c[3])
        : "r"(a[0]), "r"(a[1]), "r"(a[2]), "r"(a[3]), "r"(b[0]), "r"(b[1]));
}
__device__ __forceinline__ void ldsm_x4(uint32_t* r, uint32_t saddr) {
    asm volatile("ldmatrix.sync.aligned.m8n8.x4.shared.b16 {%0,%1,%2,%3}, [%4];"
                 : "=r"(r[0]), "=r"(r[1]), "=r"(r[2]), "=r"(r[3]) : "r"(saddr));
}
__device__ __forceinline__ uint32_t pack_h2(float x, float y) {
    __half2 h = __float22half2_rn(make_float2(x, y));
    return *(uint32_t*)&h;
}
__device__ __forceinline__ void ld4h(const __half* p, float* o) {
    __half2 a = *(const __half2*)p;
    __half2 b = *(const __half2*)(p + 2);
    o[0] = __low2float(a); o[1] = __high2float(a);
    o[2] = __low2float(b); o[3] = __high2float(b);
}
__device__ __forceinline__ void st4h(__half* p, float4 v) {
    *(__half2*)p = __float22half2_rn(make_float2(v.x, v.y));
    *(__half2*)(p + 2) = __float22half2_rn(make_float2(v.z, v.w));
}

// ---------------- fp16 tensor-core GEMM: C[M,N] = A @ B^T + bias ----------
static constexpr int GEMM_RSTRIDE_B = 80;
static constexpr int GEMM_A_BYTES = 128 * GEMM_RSTRIDE_B;
static constexpr int GEMM_B_BYTES = 256 * GEMM_RSTRIDE_B;
static constexpr int GEMM_BUF_BYTES = GEMM_A_BYTES + GEMM_B_BYTES;
static constexpr int GEMM_SMEM = 2 * GEMM_BUF_BYTES;
static constexpr int GEMM_TPB = 512;

template <bool RELU, bool AH, bool CH>
__global__ __launch_bounds__(GEMM_TPB, 1) void mma_gemm_kernel(
    const void* __restrict__ A_, const float* __restrict__ B,
    const float* __restrict__ bias, void* __restrict__ C_,
    int M, int N, int K) {
    extern __shared__ char smc[];
    const int tid = threadIdx.x;
    const int lane = tid & 31;
    const int warp = tid >> 5;
    const int wm = warp & 1;
    const int wn = warp >> 1;
    const int m0 = blockIdx.y * 128;
    const int n0 = blockIdx.x * 256;
    const uint32_t sbase = smem_u32(smc);
    const int ar = tid >> 3, ac = tid & 7;
    const int g = lane >> 3, r8 = lane & 7;
    const uint32_t a_l = (uint32_t)((wm * 64 + (g & 1) * 8 + r8) * GEMM_RSTRIDE_B +
                                    (g >> 1) * 16);
    const uint32_t b_l = (uint32_t)((wn * 32 + (g & 1) * 8 + r8) * GEMM_RSTRIDE_B +
                                    (g >> 1) * 16) + GEMM_A_BYTES;

    float acc[4][4][4];
#pragma unroll
    for (int i = 0; i < 4; i++)
#pragma unroll
        for (int j = 0; j < 4; j++)
#pragma unroll
            for (int q = 0; q < 4; q++) acc[i][j][q] = 0.f;

    const int niter = K >> 5;
    float4 pa[2], pb[4];
    uint2 pa16[2];

#define LDG_TILE(k0i)                                                              \
    do {                                                                           \
        const float* Bg = B + (size_t)n0 * K + (k0i) * 32;                         \
        if (AH) {                                                                  \
            const __half* Ag = (const __half*)A_ + (size_t)m0 * K + (k0i) * 32;    \
            _Pragma("unroll")                                                      \
            for (int i = 0; i < 2; i++)                                            \
                pa16[i] = *(const uint2*)&Ag[(size_t)(ar + i * 64) * K + ac * 4];  \
        } else {                                                                   \
            const float* Ag = (const float*)A_ + (size_t)m0 * K + (k0i) * 32;      \
            _Pragma("unroll")                                                      \
            for (int i = 0; i < 2; i++)                                            \
                pa[i] = *(const float4*)&Ag[(size_t)(ar + i * 64) * K + ac * 4];   \
        }                                                                          \
        _Pragma("unroll")                                                          \
        for (int i = 0; i < 4; i++)                                                \
            pb[i] = *(const float4*)&Bg[(size_t)(ar + i * 64) * K + ac * 4];       \
    } while (0)

#define STS_TILE(buf)                                                              \
    do {                                                                           \
        char* Ab_ = smc + (buf) * GEMM_BUF_BYTES;                                  \
        char* Bb_ = Ab_ + GEMM_A_BYTES;                                            \
        _Pragma("unroll")                                                          \
        for (int i = 0; i < 2; i++) {                                              \
            uint2* p = (uint2*)(Ab_ + (ar + i * 64) * GEMM_RSTRIDE_B + ac * 8);    \
            if (AH) *p = pa16[i];                                                  \
            else                                                                   \
                *p = make_uint2(pack_h2(pa[i].x, pa[i].y),                         \
                                pack_h2(pa[i].z, pa[i].w));                        \
        }                                                                          \
        _Pragma("unroll")                                                          \
        for (int i = 0; i < 4; i++) {                                              \
            uint2* p = (uint2*)(Bb_ + (ar + i * 64) * GEMM_RSTRIDE_B + ac * 8);    \
            *p = make_uint2(pack_h2(pb[i].x, pb[i].y), pack_h2(pb[i].z, pb[i].w)); \
        }                                                                          \
    } while (0)

    LDG_TILE(0);
    STS_TILE(0);
    __syncthreads();
    if (niter > 1) LDG_TILE(1);

    for (int k0i = 0; k0i < niter; k0i++) {
        if (k0i + 1 < niter) STS_TILE((k0i + 1) & 1);
        if (k0i + 2 < niter) LDG_TILE(k0i + 2);

        const uint32_t base = sbase + (uint32_t)((k0i & 1) * GEMM_BUF_BYTES);
        const uint32_t aaddr = base + a_l;
        const uint32_t baddr = base + b_l;
#pragma unroll
        for (int ks = 0; ks < 2; ks++) {
            uint32_t a[4][4];
#pragma unroll
            for (int i = 0; i < 4; i++)
                ldsm_x4(a[i], aaddr + (uint32_t)(i * 16 * GEMM_RSTRIDE_B + ks * 32));
            uint32_t b[4][2];
#pragma unroll
            for (int jj = 0; jj < 2; jj++) {
                uint32_t t[4];
                ldsm_x4(t, baddr + (uint32_t)(jj * 16 * GEMM_RSTRIDE_B + ks * 32));
                b[2 * jj][0] = t[0]; b[2 * jj][1] = t[2];
                b[2 * jj + 1][0] = t[1]; b[2 * jj + 1][1] = t[3];
            }
#pragma unroll
            for (int i = 0; i < 4; i++)
#pragma unroll
                for (int j = 0; j < 4; j++) mma_f16(acc[i][j], a[i], b[j]);
        }
        __syncthreads();
    }

#pragma unroll
    for (int i = 0; i < 4; i++) {
        int mr = m0 + wm * 64 + i * 16 + (lane >> 2);
#pragma unroll
        for (int j = 0; j < 4; j++) {
            int nc = n0 + wn * 32 + j * 8 + (lane & 3) * 2;
            float b0 = bias[nc], b1 = bias[nc + 1];
            float v0 = acc[i][j][0] + b0;
            float v1 = acc[i][j][1] + b1;
            float v2 = acc[i][j][2] + b0;
            float v3 = acc[i][j][3] + b1;
            if (RELU) {
                v0 = fmaxf(v0, 0.f); v1 = fmaxf(v1, 0.f);
                v2 = fmaxf(v2, 0.f); v3 = fmaxf(v3, 0.f);
            }
            if (CH) {
                __half* C = (__half*)C_;
                *(__half2*)&C[(size_t)mr * N + nc] =
                    __float22half2_rn(make_float2(v0, v1));
                *(__half2*)&C[(size_t)(mr + 8) * N + nc] =
                    __float22half2_rn(make_float2(v2, v3));
            } else {
                float* C = (float*)C_;
                *(float2*)&C[(size_t)mr * N + nc] = make_float2(v0, v1);
                *(float2*)&C[(size_t)(mr + 8) * N + nc] = make_float2(v2, v3);
            }
        }
    }
#undef LDG_TILE
#undef STS_TILE
}

// ---------------- CSR build ----------------
__global__ void csr_count_kernel(const int* __restrict__ ei, int* __restrict__ count) {
    int e = (int)((size_t)blockIdx.x * blockDim.x + threadIdx.x);
    if (e >= N_EDGES) return;
    atomicAdd(&count[ei[N_EDGES + e]], 1);
}

// single-block scan over N_NODES counts -> rowstart (exclusive) + cursor copy
__global__ void csr_scan_kernel(const int* __restrict__ count,
                                int* __restrict__ rowstart, int* __restrict__ cursor) {
    __shared__ int ssum[1024];
    const int t = threadIdx.x;
    const int CH = N_NODES / 1024;   // 128
    const int base = t * CH;
    int s = 0;
    for (int i = 0; i < CH; i++) s += count[base + i];
    ssum[t] = s;
    __syncthreads();
    for (int off = 1; off < 1024; off <<= 1) {
        int v = (t >= off) ? ssum[t - off] : 0;
        __syncthreads();
        ssum[t] += v;
        __syncthreads();
    }
    int run = (t == 0) ? 0 : ssum[t - 1];
    for (int i = 0; i < CH; i++) {
        rowstart[base + i] = run;
        cursor[base + i] = run;
        run += count[base + i];
    }
    if (t == 1023) rowstart[N_NODES] = run;
}

__global__ void csr_fill_kernel(const int* __restrict__ ei, int* __restrict__ cursor,
                                int* __restrict__ csr_src, int* __restrict__ csr_eid) {
    int e = (int)((size_t)blockIdx.x * blockDim.x + threadIdx.x);
    if (e >= N_EDGES) return;
    int d = ei[N_EDGES + e];
    int pos = atomicAdd(&cursor[d], 1);
    csr_src[pos] = ei[e];
    csr_eid[pos] = e;
}

// ---------------- edge gather: agg[n] = x[n] + sum relu(x[src] + e) --------
__global__ void edge_gather_kernel(const int* __restrict__ rowstart,
                                   const int* __restrict__ csr_src,
                                   const int* __restrict__ csr_eid,
                                   const float* __restrict__ x,
                                   const __half* __restrict__ e,
                                   float* __restrict__ agg) {
    size_t idx = (size_t)blockIdx.x * blockDim.x + threadIdx.x;
    if (idx >= (size_t)N_NODES * 64) return;
    int n = (int)(idx >> 6);
    int c = (int)(idx & 63);
    int beg = rowstart[n], end = rowstart[n + 1];
    float4 acc = *(const float4*)&x[(size_t)n * D + c * 4];
    for (int k = beg; k < end; k++) {
        int s = csr_src[k];
        int eid = csr_eid[k];
        float4 xv = *(const float4*)&x[(size_t)s * D + c * 4];
        float ev[4];
        ld4h(e + (size_t)eid * D + c * 4, ev);
        acc.x += fmaxf(xv.x + ev[0], 0.f);
        acc.y += fmaxf(xv.y + ev[1], 0.f);
        acc.z += fmaxf(xv.z + ev[2], 0.f);
        acc.w += fmaxf(xv.w + ev[3], 0.f);
    }
    *(float4*)&agg[(size_t)n * D + c * 4] = acc;
}

// ---------------- weight transpose ----------------
__global__ void transpose_kernel(const float* __restrict__ in, float* __restrict__ out,
                                 int R, int C) {
    __shared__ float t[32][33];
    int c0 = blockIdx.x * 32, r0 = blockIdx.y * 32;
    for (int i = threadIdx.y; i < 32; i += 8)
        t[i][threadIdx.x] = in[(size_t)(r0 + i) * C + c0 + threadIdx.x];
    __syncthreads();
    for (int i = threadIdx.y; i < 32; i += 8)
        out[(size_t)(c0 + i) * R + r0 + threadIdx.x] = t[threadIdx.x][i];
}

// ---------------- encoders ----------------
__global__ void atom_encode_kernel(const int* __restrict__ xa,
                                   const float* __restrict__ emb,
                                   float* __restrict__ hx0, float* __restrict__ hx1) {
    size_t idx = (size_t)blockIdx.x * blockDim.x + threadIdx.x;
    if (idx >= (size_t)N_NODES * 64) return;
    int n = (int)(idx >> 6);
    int c = (int)(idx & 63);
    float4 acc = make_float4(0.f, 0.f, 0.f, 0.f);
#pragma unroll
    for (int i = 0; i < 9; i++) {
        int t = xa[n * 9 + i];
        const float4 v = *(const float4*)&emb[((size_t)(i * 120 + t)) * D + c * 4];
        acc.x += v.x; acc.y += v.y; acc.z += v.z; acc.w += v.w;
    }
    size_t o = (size_t)n * D + c * 4;
    *(float4*)&hx0[o] = acc;
    *(float4*)&hx1[o] = acc;
}

__global__ void bond_encode_kernel(const int* __restrict__ ea,
                                   const float* __restrict__ emb,
                                   __half* __restrict__ e_out) {
    __shared__ float tab[3 * 6 * D];
    for (int i = threadIdx.x; i < 3 * 6 * D; i += blockDim.x) tab[i] = emb[i];
    __syncthreads();
    size_t total = (size_t)N_EDGES * 64;
    size_t stride = (size_t)gridDim.x * blockDim.x;
    for (size_t idx = (size_t)blockIdx.x * blockDim.x + threadIdx.x; idx < total;
         idx += stride) {
        int n = (int)(idx >> 6);
        int c = (int)(idx & 63);
        float4 acc = make_float4(0.f, 0.f, 0.f, 0.f);
#pragma unroll
        for (int i = 0; i < 3; i++) {
            int t = ea[n * 3 + i];
            const float4 v = *(const float4*)&tab[(i * 6 + t) * D + c * 4];
            acc.x += v.x; acc.y += v.y; acc.z += v.z; acc.w += v.w;
        }
        st4h(e_out + (size_t)n * D + c * 4, acc);
    }
}

// ---------------- GRU / LSTM gates ----------------
__global__ void gru_gate_kernel(const __half* __restrict__ gi,
                                const __half* __restrict__ gh,
                                float* __restrict__ hx) {
    size_t idx = (size_t)blockIdx.x * blockDim.x + threadIdx.x;
    if (idx >= (size_t)N_NODES * 64) return;
    int n = (int)(idx >> 6);
    int c = (int)(idx & 63);
    size_t base = (size_t)n * 3 * D + c * 4;
    float ir[4], iz[4], in_[4], hr[4], hz[4], hn[4];
    ld4h(gi + base, ir); ld4h(gi + base + D, iz); ld4h(gi + base + 2 * D, in_);
    ld4h(gh + base, hr); ld4h(gh + base + D, hz); ld4h(gh + base + 2 * D, hn);
    size_t hidx = (size_t)n * D + c * 4;
    float4 hp = *(const float4*)&hx[hidx];
    float hpv[4] = {hp.x, hp.y, hp.z, hp.w};
    float ov[4];
#pragma unroll
    for (int q = 0; q < 4; q++) {
        float r = sigmoidf_(ir[q] + hr[q]);
        float z = sigmoidf_(iz[q] + hz[q]);
        float nn = tanhf(in_[q] + r * hn[q]);
        ov[q] = (1.0f - z) * nn + z * hpv[q];
    }
    *(float4*)&hx[hidx] = make_float4(ov[0], ov[1], ov[2], ov[3]);
}

__global__ void lstm_gate_kernel(const float* __restrict__ g1,
                                 const float* __restrict__ g2,
                                 float* __restrict__ hs, float* __restrict__ cs) {
    size_t idx = (size_t)blockIdx.x * blockDim.x + threadIdx.x;
    if (idx >= (size_t)N_GRAPHS * D) return;
    int b = (int)(idx >> 8);
    int d = (int)(idx & 255);
    size_t base = (size_t)b * 4 * D + d;
    float ig = sigmoidf_(g1[base] + g2[base]);
    float fg = sigmoidf_(g1[base + D] + g2[base + D]);
    float gg = tanhf(g1[base + 2 * D] + g2[base + 2 * D]);
    float og = sigmoidf_(g1[base + 3 * D] + g2[base + 3 * D]);
    float c = fg * cs[idx] + ig * gg;
    cs[idx] = c;
    hs[idx] = og * tanhf(c);
}

// ---------------- Set2Set attention ----------------
__global__ void s2s_prep_kernel(float* __restrict__ qstar,
                                const float* __restrict__ hs,
                                float* __restrict__ m, float* __restrict__ norm) {
    size_t i = (size_t)blockIdx.x * blockDim.x + threadIdx.x;
    if (i < N_GRAPHS) { m[i] = -INFINITY; norm[i] = 0.f; }
    if (i < (size_t)N_GRAPHS * D) {
        int b = (int)(i >> 8);
        int d = (int)(i & 255);
        qstar[(size_t)b * 2 * D + d] = hs[i];
        qstar[(size_t)b * 2 * D + D + d] = 0.f;
    }
}

__global__ void attn_prod_kernel(const float* __restrict__ hs,
                                 const float* __restrict__ x,
                                 const int* __restrict__ batch,
                                 float* __restrict__ prod) {
    int warp = (int)(((size_t)blockIdx.x * blockDim.x + threadIdx.x) >> 5);
    int lane = threadIdx.x & 31;
    if (warp >= N_NODES) return;
    int b = batch[warp];
    const float* q = hs + (size_t)b * D;
    const float* xv = x + (size_t)warp * D;
    float s = 0.f;
#pragma unroll
    for (int j = 0; j < D / 32; j++) s += q[lane + j * 32] * xv[lane + j * 32];
#pragma unroll
    for (int o = 16; o; o >>= 1) s += __shfl_xor_sync(0xFFFFFFFFu, s, o);
    if (lane == 0) prod[warp] = s;
}

__global__ void attn_max_kernel(const int* __restrict__ batch,
                                const float* __restrict__ prod,
                                float* __restrict__ m) {
    int n = (int)((size_t)blockIdx.x * blockDim.x + threadIdx.x);
    if (n >= N_NODES) return;
    atomicMaxFloat(&m[batch[n]], prod[n]);
}

__global__ void attn_expnorm_kernel(const int* __restrict__ batch,
                                    float* __restrict__ prod,
                                    const float* __restrict__ m,
                                    float* __restrict__ norm) {
    int n = (int)((size_t)blockIdx.x * blockDim.x + threadIdx.x);
    if (n >= N_NODES) return;
    int b = batch[n];
    float a = expf(prod[n] - m[b]);
    prod[n] = a;
    atomicAdd(&norm[b], a);
}

__global__ void attn_scatter_kernel(const int* __restrict__ batch,
                                    const float* __restrict__ prod,
                                    const float* __restrict__ norm,
                                    const float* __restrict__ x,
                                    float* __restrict__ qstar) {
    size_t idx = (size_t)blockIdx.x * blockDim.x + threadIdx.x;
    if (idx >= (size_t)N_NODES * 64) return;
    int n = (int)(idx >> 6);
    int c = (int)(idx & 63);
    int b = batch[n];
    float coef = prod[n] / (norm[b] + EPS);
    float4 xv = *(const float4*)&x[(size_t)n * D + c * 4];
    float4 v = make_float4(coef * xv.x, coef * xv.y, coef * xv.z, coef * xv.w);
    atomicAdd((float4*)&qstar[(size_t)b * 2 * D + D + c * 4], v);
}

__global__ void fc_kernel(const float* __restrict__ qstar,
                          const float* __restrict__ fw,
                          const float* __restrict__ fb,
                          float* __restrict__ out) {
    int warp = (int)(((size_t)blockIdx.x * blockDim.x + threadIdx.x) >> 5);
    int lane = threadIdx.x & 31;
    if (warp >= N_GRAPHS) return;
    float s = 0.f;
#pragma unroll
    for (int j = 0; j < (2 * D) / 32; j++)
        s += qstar[(size_t)warp * 2 * D + lane + j * 32] * fw[lane + j * 32];
#pragma unroll
    for (int o = 16; o; o >>= 1) s += __shfl_xor_sync(0xFFFFFFFFu, s, o);
    if (lane == 0) out[warp] = s + fb[0];
}

// ---------------- launch ----------------
extern "C" void kernel_launch(void* const* d_in, const int* in_sizes, int n_in,
                              void* d_out, int out_size) {
    const int* x_atoms = (const int*)d_in[0];
    const int* edge_index = (const int*)d_in[1];
    const int* edge_attr = (const int*)d_in[2];
    const int* batch = (const int*)d_in[3];
    const float* atom_emb = (const float*)d_in[4];
    const float* bond_emb = (const float*)d_in[5];
    const float* gin_w1 = (const float*)d_in[6];
    const float* gin_b1 = (const float*)d_in[7];
    const float* gin_w2 = (const float*)d_in[8];
    const float* gin_b2 = (const float*)d_in[9];
    const float* gru_wih = (const float*)d_in[10];
    const float* gru_whh = (const float*)d_in[11];
    const float* gru_bih = (const float*)d_in[12];
    const float* gru_bhh = (const float*)d_in[13];
    const float* lstm_wih = (const float*)d_in[14];
    const float* lstm_whh = (const float*)d_in[15];
    const float* lstm_bih = (const float*)d_in[16];
    const float* lstm_bhh = (const float*)d_in[17];
    const float* fc_w = (const float*)d_in[18];
    const float* fc_b = (const float*)d_in[19];
    float* out = (float*)d_out;

    float *hx0, *hx1, *agg, *g1, *g2, *hs, *cs, *qstar, *prod, *mbuf, *norm,
        *w1t, *w2t;
    __half *e16, *t16, *xconv16, *gi16, *gh16;
    int *count, *rowstart, *cursor, *csr_src, *csr_eid;
    cudaGetSymbolAddress((void**)&hx0, g_hx0);
    cudaGetSymbolAddress((void**)&hx1, g_hx1);
    cudaGetSymbolAddress((void**)&e16, g_e16);
    cudaGetSymbolAddress((void**)&agg, g_agg);
    cudaGetSymbolAddress((void**)&t16, g_t16);
    cudaGetSymbolAddress((void**)&xconv16, g_xconv16);
    cudaGetSymbolAddress((void**)&gi16, g_gi16);
    cudaGetSymbolAddress((void**)&gh16, g_gh16);
    cudaGetSymbolAddress((void**)&g1, g_g1);
    cudaGetSymbolAddress((void**)&g2, g_g2);
    cudaGetSymbolAddress((void**)&hs, g_hs);
    cudaGetSymbolAddress((void**)&cs, g_cs);
    cudaGetSymbolAddress((void**)&qstar, g_qstar);
    cudaGetSymbolAddress((void**)&prod, g_prod);
    cudaGetSymbolAddress((void**)&mbuf, g_m);
    cudaGetSymbolAddress((void**)&norm, g_norm);
    cudaGetSymbolAddress((void**)&w1t, g_w1t);
    cudaGetSymbolAddress((void**)&w2t, g_w2t);
    cudaGetSymbolAddress((void**)&count, g_count);
    cudaGetSymbolAddress((void**)&rowstart, g_rowstart);
    cudaGetSymbolAddress((void**)&cursor, g_cursor);
    cudaGetSymbolAddress((void**)&csr_src, g_csr_src);
    cudaGetSymbolAddress((void**)&csr_eid, g_csr_eid);

    cudaFuncSetAttribute(mma_gemm_kernel<true, false, true>,
                         cudaFuncAttributeMaxDynamicSharedMemorySize, GEMM_SMEM);
    cudaFuncSetAttribute(mma_gemm_kernel<false, true, true>,
                         cudaFuncAttributeMaxDynamicSharedMemorySize, GEMM_SMEM);
    cudaFuncSetAttribute(mma_gemm_kernel<false, false, true>,
                         cudaFuncAttributeMaxDynamicSharedMemorySize, GEMM_SMEM);
    cudaFuncSetAttribute(mma_gemm_kernel<false, false, false>,
                         cudaFuncAttributeMaxDynamicSharedMemorySize, GEMM_SMEM);

    const int TPB = 256;

    transpose_kernel<<<dim3(512 / 32, 256 / 32), dim3(32, 8)>>>(gin_w1, w1t, 256, 512);
    transpose_kernel<<<dim3(256 / 32, 512 / 32), dim3(32, 8)>>>(gin_w2, w2t, 512, 256);

    // CSR build (once per call)
    cudaMemsetAsync(count, 0, N_NODES * sizeof(int));
    csr_count_kernel<<<N_EDGES / TPB, TPB>>>(edge_index, count);
    csr_scan_kernel<<<1, 1024>>>(count, rowstart, cursor);
    csr_fill_kernel<<<N_EDGES / TPB, TPB>>>(edge_index, cursor, csr_src, csr_eid);

    atom_encode_kernel<<<(N_NODES * 64) / TPB, TPB>>>(x_atoms, atom_emb, hx0, hx1);
    bond_encode_kernel<<<2048, TPB>>>(edge_attr, bond_emb, e16);
    cudaMemsetAsync(hs, 0, (size_t)N_GRAPHS * D * sizeof(float));
    cudaMemsetAsync(cs, 0, (size_t)N_GRAPHS * D * sizeof(float));
    cudaMemsetAsync(qstar, 0, (size_t)N_GRAPHS * 2 * D * sizeof(float));

    for (int layer = 0; layer < 3; layer++) {
        edge_gather_kernel<<<(N_NODES * 64) / TPB, TPB>>>(rowstart, csr_src, csr_eid,
                                                          hx1, e16, agg);
        // GIN MLP: agg(fp32) -> t16 -> xconv16
        mma_gemm_kernel<true, false, true>
            <<<dim3(512 / 256, N_NODES / 128), GEMM_TPB, GEMM_SMEM>>>(
                agg, w1t, gin_b1, t16, N_NODES, 512, 256);
        mma_gemm_kernel<false, true, true>
            <<<dim3(256 / 256, N_NODES / 128), GEMM_TPB, GEMM_SMEM>>>(
                t16, w2t, gin_b2, xconv16, N_NODES, 256, 512);
        // GRU layer 0
        mma_gemm_kernel<false, true, true>
            <<<dim3(768 / 256, N_NODES / 128), GEMM_TPB, GEMM_SMEM>>>(
                xconv16, gru_wih, gru_bih, gi16, N_NODES, 768, 256);
        mma_gemm_kernel<false, false, true>
            <<<dim3(768 / 256, N_NODES / 128), GEMM_TPB, GEMM_SMEM>>>(
                hx0, gru_whh, gru_bhh, gh16, N_NODES, 768, 256);
        gru_gate_kernel<<<(N_NODES * 64) / TPB, TPB>>>(gi16, gh16, hx0);
        // GRU layer 1
        mma_gemm_kernel<false, false, true>
            <<<dim3(768 / 256, N_NODES / 128), GEMM_TPB, GEMM_SMEM>>>(
                hx0, gru_wih + 768 * 256, gru_bih + 768, gi16, N_NODES, 768, 256);
        mma_gemm_kernel<false, false, true>
            <<<dim3(768 / 256, N_NODES / 128), GEMM_TPB, GEMM_SMEM>>>(
                hx1, gru_whh + 768 * 256, gru_bhh + 768, gh16, N_NODES, 768, 256);
        gru_gate_kernel<<<(N_NODES * 64) / TPB, TPB>>>(gi16, gh16, hx1);
    }

    for (int step = 0; step < 3; step++) {
        mma_gemm_kernel<false, false, false>
            <<<dim3(1024 / 256, N_GRAPHS / 128), GEMM_TPB, GEMM_SMEM>>>(
                qstar, lstm_wih, lstm_bih, g1, N_GRAPHS, 1024, 512);
        mma_gemm_kernel<false, false, false>
            <<<dim3(1024 / 256, N_GRAPHS / 128), GEMM_TPB, GEMM_SMEM>>>(
                hs, lstm_whh, lstm_bhh, g2, N_GRAPHS, 1024, 256);
        lstm_gate_kernel<<<(N_GRAPHS * D) / TPB, TPB>>>(g1, g2, hs, cs);
        s2s_prep_kernel<<<(N_GRAPHS * D) / TPB, TPB>>>(qstar, hs, mbuf, norm);
        attn_prod_kernel<<<(N_NODES * 32) / TPB, TPB>>>(hs, hx1, batch, prod);
        attn_max_kernel<<<N_NODES / TPB, TPB>>>(batch, prod, mbuf);
        attn_expnorm_kernel<<<N_NODES / TPB, TPB>>>(batch, prod, mbuf, norm);
        attn_scatter_kernel<<<(N_NODES * 64) / TPB, TPB>>>(batch, prod, norm, hx1, qstar);
    }

    fc_kernel<<<(N_GRAPHS * 32) / TPB, TPB>>>(qstar, fc_w, fc_b, out);
}

// round 13
// speedup vs baseline: 1.0818x; 1.0476x over previous
#include <cuda_runtime.h>
#include <cuda_bf16.h>
#include <cuda_fp16.h>
#include <math.h>
#include <stdint.h>

#define N_NODES 131072
#define N_EDGES 524288
#define N_GRAPHS 4096
#define D 256
#define EPS 1e-10f

// ---------------- scratch (device globals; no allocation allowed) ----------
__device__ float g_hx0[N_NODES * D];
__device__ float g_hx1[N_NODES * D];          // aliases x
__device__ __half g_e16[N_EDGES * D];         // bond features (fp16)
__device__ float g_agg[N_NODES * D];
__device__ __half g_t16[N_NODES * 2 * D];
__device__ __half g_xconv16[N_NODES * D];
__device__ __half g_gi16[N_NODES * 3 * D];
__device__ __half g_gh16[N_NODES * 3 * D];
__device__ float g_g1[N_GRAPHS * 4 * D];
__device__ float g_g2[N_GRAPHS * 4 * D];
__device__ float g_hs[N_GRAPHS * D];
__device__ float g_cs[N_GRAPHS * D];
__device__ float g_qstar[N_GRAPHS * 2 * D];
__device__ float g_prod[N_NODES];
__device__ float g_m[N_GRAPHS];
__device__ float g_norm[N_GRAPHS];
__device__ float g_w1t[512 * 256];
__device__ float g_w2t[256 * 512];
// CSR (built once per call)
__device__ int g_count[N_NODES];
__device__ int g_rowstart[N_NODES + 1];
__device__ int g_cursor[N_NODES];
__device__ int g_csr_src[N_EDGES];
__device__ int g_csr_eid[N_EDGES];
__device__ int g_blocksum[128];

// ---------------- helpers ----------------
__device__ __forceinline__ uint32_t smem_u32(const void* p) {
    uint32_t a;
    asm("{ .reg .u64 t; cvta.to.shared.u64 t, %1; cvt.u32.u64 %0, t; }" : "=r"(a) : "l"(p));
    return a;
}
__device__ __forceinline__ void atomicMaxFloat(float* addr, float val) {
    int* ia = (int*)addr;
    int cur = __float_as_int(*(volatile float*)addr);
    while (__int_as_float(cur) < val) {
        int old = atomicCAS(ia, cur, __float_as_int(val));
        if (old == cur) break;
        cur = old;
    }
}
__device__ __forceinline__ float sigmoidf_(float x) { return 1.0f / (1.0f + expf(-x)); }
__device__ __forceinline__ void mma_f16(float* c, const uint32_t* a, const uint32_t* b) {
    asm volatile(
        "mma.sync.aligned.m16n8k16.row.col.f32.f16.f16.f32 "
        "{%0,%1,%2,%3}, {%4,%5,%6,%7}, {%8,%9}, {%0,%1,%2,%3};"
        : "+f"(c[0]), "+f"(c[1]), "+f"(c[2]), "+f"(c[3])
        : "r"(a[0]), "r"(a[1]), "r"(a[2]), "r"(a[3]), "r"(b[0]), "r"(b[1]));
}
__device__ __forceinline__ void ldsm_x4(uint32_t* r, uint32_t saddr) {
    asm volatile("ldmatrix.sync.aligned.m8n8.x4.shared.b16 {%0,%1,%2,%3}, [%4];"
                 : "=r"(r[0]), "=r"(r[1]), "=r"(r[2]), "=r"(r[3]) : "r"(saddr));
}
__device__ __forceinline__ uint32_t pack_h2(float x, float y) {
    __half2 h = __float22half2_rn(make_float2(x, y));
    return *(uint32_t*)&h;
}
__device__ __forceinline__ void ld4h(const __half* p, float* o) {
    __half2 a = *(const __half2*)p;
    __half2 b = *(const __half2*)(p + 2);
    o[0] = __low2float(a); o[1] = __high2float(a);
    o[2] = __low2float(b); o[3] = __high2float(b);
}
__device__ __forceinline__ void st4h(__half* p, float4 v) {
    *(__half2*)p = __float22half2_rn(make_float2(v.x, v.y));
    *(__half2*)(p + 2) = __float22half2_rn(make_float2(v.z, v.w));
}

// ---------------- fp16 tensor-core GEMM: C[M,N] = A @ B^T + bias ----------
static constexpr int GEMM_RSTRIDE_B = 80;
static constexpr int GEMM_A_BYTES = 128 * GEMM_RSTRIDE_B;
static constexpr int GEMM_B_BYTES = 256 * GEMM_RSTRIDE_B;
static constexpr int GEMM_BUF_BYTES = GEMM_A_BYTES + GEMM_B_BYTES;
static constexpr int GEMM_SMEM = 2 * GEMM_BUF_BYTES;
static constexpr int GEMM_TPB = 512;

template <bool RELU, bool AH, bool CH>
__global__ __launch_bounds__(GEMM_TPB, 1) void mma_gemm_kernel(
    const void* __restrict__ A_, const float* __restrict__ B,
    const float* __restrict__ bias, void* __restrict__ C_,
    int M, int N, int K) {
    extern __shared__ char smc[];
    const int tid = threadIdx.x;
    const int lane = tid & 31;
    const int warp = tid >> 5;
    const int wm = warp & 1;
    const int wn = warp >> 1;
    const int m0 = blockIdx.y * 128;
    const int n0 = blockIdx.x * 256;
    const uint32_t sbase = smem_u32(smc);
    const int ar = tid >> 3, ac = tid & 7;
    const int g = lane >> 3, r8 = lane & 7;
    const uint32_t a_l = (uint32_t)((wm * 64 + (g & 1) * 8 + r8) * GEMM_RSTRIDE_B +
                                    (g >> 1) * 16);
    const uint32_t b_l = (uint32_t)((wn * 32 + (g & 1) * 8 + r8) * GEMM_RSTRIDE_B +
                                    (g >> 1) * 16) + GEMM_A_BYTES;

    float acc[4][4][4];
#pragma unroll
    for (int i = 0; i < 4; i++)
#pragma unroll
        for (int j = 0; j < 4; j++)
#pragma unroll
            for (int q = 0; q < 4; q++) acc[i][j][q] = 0.f;

    const int niter = K >> 5;
    float4 pa[2], pb[4];
    uint2 pa16[2];

#define LDG_TILE(k0i)                                                              \
    do {                                                                           \
        const float* Bg = B + (size_t)n0 * K + (k0i) * 32;                         \
        if (AH) {                                                                  \
            const __half* Ag = (const __half*)A_ + (size_t)m0 * K + (k0i) * 32;    \
            _Pragma("unroll")                                                      \
            for (int i = 0; i < 2; i++)                                            \
                pa16[i] = *(const uint2*)&Ag[(size_t)(ar + i * 64) * K + ac * 4];  \
        } else {                                                                   \
            const float* Ag = (const float*)A_ + (size_t)m0 * K + (k0i) * 32;      \
            _Pragma("unroll")                                                      \
            for (int i = 0; i < 2; i++)                                            \
                pa[i] = *(const float4*)&Ag[(size_t)(ar + i * 64) * K + ac * 4];   \
        }                                                                          \
        _Pragma("unroll")                                                          \
        for (int i = 0; i < 4; i++)                                                \
            pb[i] = *(const float4*)&Bg[(size_t)(ar + i * 64) * K + ac * 4];       \
    } while (0)

#define STS_TILE(buf)                                                              \
    do {                                                                           \
        char* Ab_ = smc + (buf) * GEMM_BUF_BYTES;                                  \
        char* Bb_ = Ab_ + GEMM_A_BYTES;                                            \
        _Pragma("unroll")                                                          \
        for (int i = 0; i < 2; i++) {                                              \
            uint2* p = (uint2*)(Ab_ + (ar + i * 64) * GEMM_RSTRIDE_B + ac * 8);    \
            if (AH) *p = pa16[i];                                                  \
            else                                                                   \
                *p = make_uint2(pack_h2(pa[i].x, pa[i].y),                         \
                                pack_h2(pa[i].z, pa[i].w));                        \
        }                                                                          \
        _Pragma("unroll")                                                          \
        for (int i = 0; i < 4; i++) {                                              \
            uint2* p = (uint2*)(Bb_ + (ar + i * 64) * GEMM_RSTRIDE_B + ac * 8);    \
            *p = make_uint2(pack_h2(pb[i].x, pb[i].y), pack_h2(pb[i].z, pb[i].w)); \
        }                                                                          \
    } while (0)

    LDG_TILE(0);
    STS_TILE(0);
    __syncthreads();
    if (niter > 1) LDG_TILE(1);

    for (int k0i = 0; k0i < niter; k0i++) {
        if (k0i + 1 < niter) STS_TILE((k0i + 1) & 1);
        if (k0i + 2 < niter) LDG_TILE(k0i + 2);

        const uint32_t base = sbase + (uint32_t)((k0i & 1) * GEMM_BUF_BYTES);
        const uint32_t aaddr = base + a_l;
        const uint32_t baddr = base + b_l;
#pragma unroll
        for (int ks = 0; ks < 2; ks++) {
            uint32_t a[4][4];
#pragma unroll
            for (int i = 0; i < 4; i++)
                ldsm_x4(a[i], aaddr + (uint32_t)(i * 16 * GEMM_RSTRIDE_B + ks * 32));
            uint32_t b[4][2];
#pragma unroll
            for (int jj = 0; jj < 2; jj++) {
                uint32_t t[4];
                ldsm_x4(t, baddr + (uint32_t)(jj * 16 * GEMM_RSTRIDE_B + ks * 32));
                b[2 * jj][0] = t[0]; b[2 * jj][1] = t[2];
                b[2 * jj + 1][0] = t[1]; b[2 * jj + 1][1] = t[3];
            }
#pragma unroll
            for (int i = 0; i < 4; i++)
#pragma unroll
                for (int j = 0; j < 4; j++) mma_f16(acc[i][j], a[i], b[j]);
        }
        __syncthreads();
    }

#pragma unroll
    for (int i = 0; i < 4; i++) {
        int mr = m0 + wm * 64 + i * 16 + (lane >> 2);
#pragma unroll
        for (int j = 0; j < 4; j++) {
            int nc = n0 + wn * 32 + j * 8 + (lane & 3) * 2;
            float b0 = bias[nc], b1 = bias[nc + 1];
            float v0 = acc[i][j][0] + b0;
            float v1 = acc[i][j][1] + b1;
            float v2 = acc[i][j][2] + b0;
            float v3 = acc[i][j][3] + b1;
            if (RELU) {
                v0 = fmaxf(v0, 0.f); v1 = fmaxf(v1, 0.f);
                v2 = fmaxf(v2, 0.f); v3 = fmaxf(v3, 0.f);
            }
            if (CH) {
                __half* C = (__half*)C_;
                *(__half2*)&C[(size_t)mr * N + nc] =
                    __float22half2_rn(make_float2(v0, v1));
                *(__half2*)&C[(size_t)(mr + 8) * N + nc] =
                    __float22half2_rn(make_float2(v2, v3));
            } else {
                float* C = (float*)C_;
                *(float2*)&C[(size_t)mr * N + nc] = make_float2(v0, v1);
                *(float2*)&C[(size_t)(mr + 8) * N + nc] = make_float2(v2, v3);
            }
        }
    }
#undef LDG_TILE
#undef STS_TILE
}

// ---------------- CSR build (parallel 3-phase scan) ----------------
__global__ void csr_count_kernel(const int* __restrict__ ei, int* __restrict__ count) {
    int e = (int)((size_t)blockIdx.x * blockDim.x + threadIdx.x);
    if (e >= N_EDGES) return;
    atomicAdd(&count[ei[N_EDGES + e]], 1);
}

// phase 1: 128 blocks x 256 threads; block scans 1024 counts (4/thread),
// writes partial (block-local exclusive) prefix into rowstart, total to blocksum.
__global__ void csr_scan1_kernel(const int* __restrict__ count,
                                 int* __restrict__ rowstart,
                                 int* __restrict__ blocksum) {
    __shared__ int ts[256];
    const int t = threadIdx.x;
    const int base = blockIdx.x * 1024 + t * 4;
    int c0 = count[base], c1 = count[base + 1], c2 = count[base + 2], c3 = count[base + 3];
    int local = c0 + c1 + c2 + c3;
    ts[t] = local;
    __syncthreads();
#pragma unroll
    for (int off = 1; off < 256; off <<= 1) {
        int v = (t >= off) ? ts[t - off] : 0;
        __syncthreads();
        ts[t] += v;
        __syncthreads();
    }
    int pre = ts[t] - local;       // exclusive prefix of this thread within block
    rowstart[base] = pre;
    rowstart[base + 1] = pre + c0;
    rowstart[base + 2] = pre + c0 + c1;
    rowstart[base + 3] = pre + c0 + c1 + c2;
    if (t == 255) blocksum[blockIdx.x] = ts[255];
}

// phase 2: exclusive scan of 128 block sums (one warp would do; use 128 thr)
__global__ void csr_scan2_kernel(int* __restrict__ blocksum) {
    __shared__ int ts[128];
    const int t = threadIdx.x;
    int v0 = blocksum[t];
    ts[t] = v0;
    __syncthreads();
#pragma unroll
    for (int off = 1; off < 128; off <<= 1) {
        int v = (t >= off) ? ts[t - off] : 0;
        __syncthreads();
        ts[t] += v;
        __syncthreads();
    }
    blocksum[t] = ts[t] - v0;      // exclusive
}

// phase 3: add block offsets, produce cursor; rowstart[N_NODES] = N_EDGES.
__global__ void csr_scan3_kernel(int* __restrict__ rowstart, int* __restrict__ cursor,
                                 const int* __restrict__ blocksum) {
    const int i = blockIdx.x * 1024 + threadIdx.x * 4;
    const int off = blocksum[blockIdx.x];
#pragma unroll
    for (int q = 0; q < 4; q++) {
        int v = rowstart[i + q] + off;
        rowstart[i + q] = v;
        cursor[i + q] = v;
    }
    if (blockIdx.x == 0 && threadIdx.x == 0) rowstart[N_NODES] = N_EDGES;
}

__global__ void csr_fill_kernel(const int* __restrict__ ei, int* __restrict__ cursor,
                                int* __restrict__ csr_src, int* __restrict__ csr_eid) {
    int e = (int)((size_t)blockIdx.x * blockDim.x + threadIdx.x);
    if (e >= N_EDGES) return;
    int d = ei[N_EDGES + e];
    int pos = atomicAdd(&cursor[d], 1);
    csr_src[pos] = ei[e];
    csr_eid[pos] = e;
}

// ---------------- edge gather: agg[n] = x[n] + sum relu(x[src] + e) --------
__global__ void edge_gather_kernel(const int* __restrict__ rowstart,
                                   const int* __restrict__ csr_src,
                                   const int* __restrict__ csr_eid,
                                   const float* __restrict__ x,
                                   const __half* __restrict__ e,
                                   float* __restrict__ agg) {
    size_t idx = (size_t)blockIdx.x * blockDim.x + threadIdx.x;
    if (idx >= (size_t)N_NODES * 64) return;
    int n = (int)(idx >> 6);
    int c = (int)(idx & 63);
    int beg = rowstart[n], end = rowstart[n + 1];
    float4 acc = *(const float4*)&x[(size_t)n * D + c * 4];
    for (int k = beg; k < end; k++) {
        int s = csr_src[k];
        int eid = csr_eid[k];
        float4 xv = *(const float4*)&x[(size_t)s * D + c * 4];
        float ev[4];
        ld4h(e + (size_t)eid * D + c * 4, ev);
        acc.x += fmaxf(xv.x + ev[0], 0.f);
        acc.y += fmaxf(xv.y + ev[1], 0.f);
        acc.z += fmaxf(xv.z + ev[2], 0.f);
        acc.w += fmaxf(xv.w + ev[3], 0.f);
    }
    *(float4*)&agg[(size_t)n * D + c * 4] = acc;
}

// ---------------- weight transpose ----------------
__global__ void transpose_kernel(const float* __restrict__ in, float* __restrict__ out,
                                 int R, int C) {
    __shared__ float t[32][33];
    int c0 = blockIdx.x * 32, r0 = blockIdx.y * 32;
    for (int i = threadIdx.y; i < 32; i += 8)
        t[i][threadIdx.x] = in[(size_t)(r0 + i) * C + c0 + threadIdx.x];
    __syncthreads();
    for (int i = threadIdx.y; i < 32; i += 8)
        out[(size_t)(c0 + i) * R + r0 + threadIdx.x] = t[threadIdx.x][i];
}

// ---------------- encoders ----------------
__global__ void atom_encode_kernel(const int* __restrict__ xa,
                                   const float* __restrict__ emb,
                                   float* __restrict__ hx0, float* __restrict__ hx1) {
    size_t idx = (size_t)blockIdx.x * blockDim.x + threadIdx.x;
    if (idx >= (size_t)N_NODES * 64) return;
    int n = (int)(idx >> 6);
    int c = (int)(idx & 63);
    float4 acc = make_float4(0.f, 0.f, 0.f, 0.f);
#pragma unroll
    for (int i = 0; i < 9; i++) {
        int t = xa[n * 9 + i];
        const float4 v = *(const float4*)&emb[((size_t)(i * 120 + t)) * D + c * 4];
        acc.x += v.x; acc.y += v.y; acc.z += v.z; acc.w += v.w;
    }
    size_t o = (size_t)n * D + c * 4;
    *(float4*)&hx0[o] = acc;
    *(float4*)&hx1[o] = acc;
}

__global__ void bond_encode_kernel(const int* __restrict__ ea,
                                   const float* __restrict__ emb,
                                   __half* __restrict__ e_out) {
    __shared__ float tab[3 * 6 * D];
    for (int i = threadIdx.x; i < 3 * 6 * D; i += blockDim.x) tab[i] = emb[i];
    __syncthreads();
    size_t total = (size_t)N_EDGES * 64;
    size_t stride = (size_t)gridDim.x * blockDim.x;
    for (size_t idx = (size_t)blockIdx.x * blockDim.x + threadIdx.x; idx < total;
         idx += stride) {
        int n = (int)(idx >> 6);
        int c = (int)(idx & 63);
        float4 acc = make_float4(0.f, 0.f, 0.f, 0.f);
#pragma unroll
        for (int i = 0; i < 3; i++) {
            int t = ea[n * 3 + i];
            const float4 v = *(const float4*)&tab[(i * 6 + t) * D + c * 4];
            acc.x += v.x; acc.y += v.y; acc.z += v.z; acc.w += v.w;
        }
        st4h(e_out + (size_t)n * D + c * 4, acc);
    }
}

// ---------------- GRU / LSTM gates ----------------
__global__ void gru_gate_kernel(const __half* __restrict__ gi,
                                const __half* __restrict__ gh,
                                float* __restrict__ hx) {
    size_t idx = (size_t)blockIdx.x * blockDim.x + threadIdx.x;
    if (idx >= (size_t)N_NODES * 64) return;
    int n = (int)(idx >> 6);
    int c = (int)(idx & 63);
    size_t base = (size_t)n * 3 * D + c * 4;
    float ir[4], iz[4], in_[4], hr[4], hz[4], hn[4];
    ld4h(gi + base, ir); ld4h(gi + base + D, iz); ld4h(gi + base + 2 * D, in_);
    ld4h(gh + base, hr); ld4h(gh + base + D, hz); ld4h(gh + base + 2 * D, hn);
    size_t hidx = (size_t)n * D + c * 4;
    float4 hp = *(const float4*)&hx[hidx];
    float hpv[4] = {hp.x, hp.y, hp.z, hp.w};
    float ov[4];
#pragma unroll
    for (int q = 0; q < 4; q++) {
        float r = sigmoidf_(ir[q] + hr[q]);
        float z = sigmoidf_(iz[q] + hz[q]);
        float nn = tanhf(in_[q] + r * hn[q]);
        ov[q] = (1.0f - z) * nn + z * hpv[q];
    }
    *(float4*)&hx[hidx] = make_float4(ov[0], ov[1], ov[2], ov[3]);
}

__global__ void lstm_gate_kernel(const float* __restrict__ g1,
                                 const float* __restrict__ g2,
                                 float* __restrict__ hs, float* __restrict__ cs) {
    size_t idx = (size_t)blockIdx.x * blockDim.x + threadIdx.x;
    if (idx >= (size_t)N_GRAPHS * D) return;
    int b = (int)(idx >> 8);
    int d = (int)(idx & 255);
    size_t base = (size_t)b * 4 * D + d;
    float ig = sigmoidf_(g1[base] + g2[base]);
    float fg = sigmoidf_(g1[base + D] + g2[base + D]);
    float gg = tanhf(g1[base + 2 * D] + g2[base + 2 * D]);
    float og = sigmoidf_(g1[base + 3 * D] + g2[base + 3 * D]);
    float c = fg * cs[idx] + ig * gg;
    cs[idx] = c;
    hs[idx] = og * tanhf(c);
}

// ---------------- Set2Set attention ----------------
__global__ void s2s_prep_kernel(float* __restrict__ qstar,
                                const float* __restrict__ hs,
                                float* __restrict__ m, float* __restrict__ norm) {
    size_t i = (size_t)blockIdx.x * blockDim.x + threadIdx.x;
    if (i < N_GRAPHS) { m[i] = -INFINITY; norm[i] = 0.f; }
    if (i < (size_t)N_GRAPHS * D) {
        int b = (int)(i >> 8);
        int d = (int)(i & 255);
        qstar[(size_t)b * 2 * D + d] = hs[i];
        qstar[(size_t)b * 2 * D + D + d] = 0.f;
    }
}

__global__ void attn_prod_kernel(const float* __restrict__ hs,
                                 const float* __restrict__ x,
                                 const int* __restrict__ batch,
                                 float* __restrict__ prod) {
    int warp = (int)(((size_t)blockIdx.x * blockDim.x + threadIdx.x) >> 5);
    int lane = threadIdx.x & 31;
    if (warp >= N_NODES) return;
    int b = batch[warp];
    const float* q = hs + (size_t)b * D;
    const float* xv = x + (size_t)warp * D;
    float s = 0.f;
#pragma unroll
    for (int j = 0; j < D / 32; j++) s += q[lane + j * 32] * xv[lane + j * 32];
#pragma unroll
    for (int o = 16; o; o >>= 1) s += __shfl_xor_sync(0xFFFFFFFFu, s, o);
    if (lane == 0) prod[warp] = s;
}

__global__ void attn_max_kernel(const int* __restrict__ batch,
                                const float* __restrict__ prod,
                                float* __restrict__ m) {
    int n = (int)((size_t)blockIdx.x * blockDim.x + threadIdx.x);
    if (n >= N_NODES) return;
    atomicMaxFloat(&m[batch[n]], prod[n]);
}

__global__ void attn_expnorm_kernel(const int* __restrict__ batch,
                                    float* __restrict__ prod,
                                    const float* __restrict__ m,
                                    float* __restrict__ norm) {
    int n = (int)((size_t)blockIdx.x * blockDim.x + threadIdx.x);
    if (n >= N_NODES) return;
    int b = batch[n];
    float a = expf(prod[n] - m[b]);
    prod[n] = a;
    atomicAdd(&norm[b], a);
}

__global__ void attn_scatter_kernel(const int* __restrict__ batch,
                                    const float* __restrict__ prod,
                                    const float* __restrict__ norm,
                                    const float* __restrict__ x,
                                    float* __restrict__ qstar) {
    size_t idx = (size_t)blockIdx.x * blockDim.x + threadIdx.x;
    if (idx >= (size_t)N_NODES * 64) return;
    int n = (int)(idx >> 6);
    int c = (int)(idx & 63);
    int b = batch[n];
    float coef = prod[n] / (norm[b] + EPS);
    float4 xv = *(const float4*)&x[(size_t)n * D + c * 4];
    float4 v = make_float4(coef * xv.x, coef * xv.y, coef * xv.z, coef * xv.w);
    atomicAdd((float4*)&qstar[(size_t)b * 2 * D + D + c * 4], v);
}

__global__ void fc_kernel(const float* __restrict__ qstar,
                          const float* __restrict__ fw,
                          const float* __restrict__ fb,
                          float* __restrict__ out) {
    int warp = (int)(((size_t)blockIdx.x * blockDim.x + threadIdx.x) >> 5);
    int lane = threadIdx.x & 31;
    if (warp >= N_GRAPHS) return;
    float s = 0.f;
#pragma unroll
    for (int j = 0; j < (2 * D) / 32; j++)
        s += qstar[(size_t)warp * 2 * D + lane + j * 32] * fw[lane + j * 32];
#pragma unroll
    for (int o = 16; o; o >>= 1) s += __shfl_xor_sync(0xFFFFFFFFu, s, o);
    if (lane == 0) out[warp] = s + fb[0];
}

// ---------------- launch ----------------
extern "C" void kernel_launch(void* const* d_in, const int* in_sizes, int n_in,
                              void* d_out, int out_size) {
    const int* x_atoms = (const int*)d_in[0];
    const int* edge_index = (const int*)d_in[1];
    const int* edge_attr = (const int*)d_in[2];
    const int* batch = (const int*)d_in[3];
    const float* atom_emb = (const float*)d_in[4];
    const float* bond_emb = (const float*)d_in[5];
    const float* gin_w1 = (const float*)d_in[6];
    const float* gin_b1 = (const float*)d_in[7];
    const float* gin_w2 = (const float*)d_in[8];
    const float* gin_b2 = (const float*)d_in[9];
    const float* gru_wih = (const float*)d_in[10];
    const float* gru_whh = (const float*)d_in[11];
    const float* gru_bih = (const float*)d_in[12];
    const float* gru_bhh = (const float*)d_in[13];
    const float* lstm_wih = (const float*)d_in[14];
    const float* lstm_whh = (const float*)d_in[15];
    const float* lstm_bih = (const float*)d_in[16];
    const float* lstm_bhh = (const float*)d_in[17];
    const float* fc_w = (const float*)d_in[18];
    const float* fc_b = (const float*)d_in[19];
    float* out = (float*)d_out;

    float *hx0, *hx1, *agg, *g1, *g2, *hs, *cs, *qstar, *prod, *mbuf, *norm,
        *w1t, *w2t;
    __half *e16, *t16, *xconv16, *gi16, *gh16;
    int *count, *rowstart, *cursor, *csr_src, *csr_eid, *blocksum;
    cudaGetSymbolAddress((void**)&hx0, g_hx0);
    cudaGetSymbolAddress((void**)&hx1, g_hx1);
    cudaGetSymbolAddress((void**)&e16, g_e16);
    cudaGetSymbolAddress((void**)&agg, g_agg);
    cudaGetSymbolAddress((void**)&t16, g_t16);
    cudaGetSymbolAddress((void**)&xconv16, g_xconv16);
    cudaGetSymbolAddress((void**)&gi16, g_gi16);
    cudaGetSymbolAddress((void**)&gh16, g_gh16);
    cudaGetSymbolAddress((void**)&g1, g_g1);
    cudaGetSymbolAddress((void**)&g2, g_g2);
    cudaGetSymbolAddress((void**)&hs, g_hs);
    cudaGetSymbolAddress((void**)&cs, g_cs);
    cudaGetSymbolAddress((void**)&qstar, g_qstar);
    cudaGetSymbolAddress((void**)&prod, g_prod);
    cudaGetSymbolAddress((void**)&mbuf, g_m);
    cudaGetSymbolAddress((void**)&norm, g_norm);
    cudaGetSymbolAddress((void**)&w1t, g_w1t);
    cudaGetSymbolAddress((void**)&w2t, g_w2t);
    cudaGetSymbolAddress((void**)&count, g_count);
    cudaGetSymbolAddress((void**)&rowstart, g_rowstart);
    cudaGetSymbolAddress((void**)&cursor, g_cursor);
    cudaGetSymbolAddress((void**)&csr_src, g_csr_src);
    cudaGetSymbolAddress((void**)&csr_eid, g_csr_eid);
    cudaGetSymbolAddress((void**)&blocksum, g_blocksum);

    cudaFuncSetAttribute(mma_gemm_kernel<true, false, true>,
                         cudaFuncAttributeMaxDynamicSharedMemorySize, GEMM_SMEM);
    cudaFuncSetAttribute(mma_gemm_kernel<false, true, true>,
                         cudaFuncAttributeMaxDynamicSharedMemorySize, GEMM_SMEM);
    cudaFuncSetAttribute(mma_gemm_kernel<false, false, true>,
                         cudaFuncAttributeMaxDynamicSharedMemorySize, GEMM_SMEM);
    cudaFuncSetAttribute(mma_gemm_kernel<false, false, false>,
                         cudaFuncAttributeMaxDynamicSharedMemorySize, GEMM_SMEM);

    const int TPB = 256;

    transpose_kernel<<<dim3(512 / 32, 256 / 32), dim3(32, 8)>>>(gin_w1, w1t, 256, 512);
    transpose_kernel<<<dim3(256 / 32, 512 / 32), dim3(32, 8)>>>(gin_w2, w2t, 512, 256);

    // CSR build (parallel scan)
    cudaMemsetAsync(count, 0, N_NODES * sizeof(int));
    csr_count_kernel<<<N_EDGES / TPB, TPB>>>(edge_index, count);
    csr_scan1_kernel<<<128, 256>>>(count, rowstart, blocksum);
    csr_scan2_kernel<<<1, 128>>>(blocksum);
    csr_scan3_kernel<<<128, 256>>>(rowstart, cursor, blocksum);
    csr_fill_kernel<<<N_EDGES / TPB, TPB>>>(edge_index, cursor, csr_src, csr_eid);

    atom_encode_kernel<<<(N_NODES * 64) / TPB, TPB>>>(x_atoms, atom_emb, hx0, hx1);
    bond_encode_kernel<<<2048, TPB>>>(edge_attr, bond_emb, e16);
    cudaMemsetAsync(hs, 0, (size_t)N_GRAPHS * D * sizeof(float));
    cudaMemsetAsync(cs, 0, (size_t)N_GRAPHS * D * sizeof(float));
    cudaMemsetAsync(qstar, 0, (size_t)N_GRAPHS * 2 * D * sizeof(float));

    for (int layer = 0; layer < 3; layer++) {
        edge_gather_kernel<<<(N_NODES * 64) / TPB, TPB>>>(rowstart, csr_src, csr_eid,
                                                          hx1, e16, agg);
        // GIN MLP: agg(fp32) -> t16 -> xconv16
        mma_gemm_kernel<true, false, true>
            <<<dim3(512 / 256, N_NODES / 128), GEMM_TPB, GEMM_SMEM>>>(
                agg, w1t, gin_b1, t16, N_NODES, 512, 256);
        mma_gemm_kernel<false, true, true>
            <<<dim3(256 / 256, N_NODES / 128), GEMM_TPB, GEMM_SMEM>>>(
                t16, w2t, gin_b2, xconv16, N_NODES, 256, 512);
        // GRU layer 0
        mma_gemm_kernel<false, true, true>
            <<<dim3(768 / 256, N_NODES / 128), GEMM_TPB, GEMM_SMEM>>>(
                xconv16, gru_wih, gru_bih, gi16, N_NODES, 768, 256);
        mma_gemm_kernel<false, false, true>
            <<<dim3(768 / 256, N_NODES / 128), GEMM_TPB, GEMM_SMEM>>>(
                hx0, gru_whh, gru_bhh, gh16, N_NODES, 768, 256);
        gru_gate_kernel<<<(N_NODES * 64) / TPB, TPB>>>(gi16, gh16, hx0);
        // GRU layer 1
        mma_gemm_kernel<false, false, true>
            <<<dim3(768 / 256, N_NODES / 128), GEMM_TPB, GEMM_SMEM>>>(
                hx0, gru_wih + 768 * 256, gru_bih + 768, gi16, N_NODES, 768, 256);
        mma_gemm_kernel<false, false, true>
            <<<dim3(768 / 256, N_NODES / 128), GEMM_TPB, GEMM_SMEM>>>(
                hx1, gru_whh + 768 * 256, gru_bhh + 768, gh16, N_NODES, 768, 256);
        gru_gate_kernel<<<(N_NODES * 64) / TPB, TPB>>>(gi16, gh16, hx1);
    }

    for (int step = 0; step < 3; step++) {
        mma_gemm_kernel<false, false, false>
            <<<dim3(1024 / 256, N_GRAPHS / 128), GEMM_TPB, GEMM_SMEM>>>(
                qstar, lstm_wih, lstm_bih, g1, N_GRAPHS, 1024, 512);
        mma_gemm_kernel<false, false, false>
            <<<dim3(1024 / 256, N_GRAPHS / 128), GEMM_TPB, GEMM_SMEM>>>(
                hs, lstm_whh, lstm_bhh, g2, N_GRAPHS, 1024, 256);
        lstm_gate_kernel<<<(N_GRAPHS * D) / TPB, TPB>>>(g1, g2, hs, cs);
        s2s_prep_kernel<<<(N_GRAPHS * D) / TPB, TPB>>>(qstar, hs, mbuf, norm);
        attn_prod_kernel<<<(N_NODES * 32) / TPB, TPB>>>(hs, hx1, batch, prod);
        attn_max_kernel<<<N_NODES / TPB, TPB>>>(batch, prod, mbuf);
        attn_expnorm_kernel<<<N_NODES / TPB, TPB>>>(batch, prod, mbuf, norm);
        attn_scatter_kernel<<<(N_NODES * 64) / TPB, TPB>>>(batch, prod, norm, hx1, qstar);
    }

    fc_kernel<<<(N_GRAPHS * 32) / TPB, TPB>>>(qstar, fc_w, fc_b, out);
}

// round 14
// speedup vs baseline: 1.1685x; 1.0801x over previous
#include <cuda_runtime.h>
#include <cuda_bf16.h>
#include <cuda_fp16.h>
#include <math.h>
#include <stdint.h>

#define N_NODES 131072
#define N_EDGES 524288
#define N_GRAPHS 4096
#define D 256
#define EPS 1e-10f

// ---------------- scratch (device globals; no allocation allowed) ----------
__device__ float g_hx0[N_NODES * D];
__device__ float g_hx1[N_NODES * D];          // aliases x
__device__ __half g_e16[N_EDGES * D];
__device__ __half g_agg16[N_NODES * D];       // GIN input (fp16; GEMM-only consumer)
__device__ __half g_t16[N_NODES * 2 * D];
__device__ __half g_xconv16[N_NODES * D];
__device__ __half g_gi16[N_NODES * 3 * D];
__device__ __half g_gh16[N_NODES * 3 * D];
__device__ float g_g1[N_GRAPHS * 4 * D];
__device__ float g_g2[N_GRAPHS * 4 * D];
__device__ float g_hs[N_GRAPHS * D];
__device__ float g_cs[N_GRAPHS * D];
__device__ float g_qstar[N_GRAPHS * 2 * D];
__device__ float g_prod[N_NODES];
__device__ float g_m[N_GRAPHS];
__device__ float g_norm[N_GRAPHS];
__device__ float g_w1t[512 * 256];
__device__ float g_w2t[256 * 512];
// CSR (built once per call)
__device__ int g_count[N_NODES];
__device__ int g_rowstart[N_NODES + 1];
__device__ int g_cursor[N_NODES];
__device__ int g_csr_src[N_EDGES];
__device__ int g_csr_eid[N_EDGES];
__device__ int g_blocksum[128];

// ---------------- helpers ----------------
__device__ __forceinline__ uint32_t smem_u32(const void* p) {
    uint32_t a;
    asm("{ .reg .u64 t; cvta.to.shared.u64 t, %1; cvt.u32.u64 %0, t; }" : "=r"(a) : "l"(p));
    return a;
}
__device__ __forceinline__ void atomicMaxFloat(float* addr, float val) {
    int* ia = (int*)addr;
    int cur = __float_as_int(*(volatile float*)addr);
    while (__int_as_float(cur) < val) {
        int old = atomicCAS(ia, cur, __float_as_int(val));
        if (old == cur) break;
        cur = old;
    }
}
__device__ __forceinline__ float sigmoidf_(float x) { return 1.0f / (1.0f + expf(-x)); }
__device__ __forceinline__ void mma_f16(float* c, const uint32_t* a, const uint32_t* b) {
    asm volatile(
        "mma.sync.aligned.m16n8k16.row.col.f32.f16.f16.f32 "
        "{%0,%1,%2,%3}, {%4,%5,%6,%7}, {%8,%9}, {%0,%1,%2,%3};"
        : "+f"(c[0]), "+f"(c[1]), "+f"(c[2]), "+f"(c[3])
        : "r"(a[0]), "r"(a[1]), "r"(a[2]), "r"(a[3]), "r"(b[0]), "r"(b[1]));
}
__device__ __forceinline__ void ldsm_x4(uint32_t* r, uint32_t saddr) {
    asm volatile("ldmatrix.sync.aligned.m8n8.x4.shared.b16 {%0,%1,%2,%3}, [%4];"
                 : "=r"(r[0]), "=r"(r[1]), "=r"(r[2]), "=r"(r[3]) : "r"(saddr));
}
__device__ __forceinline__ uint32_t pack_h2(float x, float y) {
    __half2 h = __float22half2_rn(make_float2(x, y));
    return *(uint32_t*)&h;
}
__device__ __forceinline__ void ld4h(const __half* p, float* o) {
    __half2 a = *(const __half2*)p;
    __half2 b = *(const __half2*)(p + 2);
    o[0] = __low2float(a); o[1] = __high2float(a);
    o[2] = __low2float(b); o[3] = __high2float(b);
}
__device__ __forceinline__ void st4h(__half* p, float4 v) {
    *(__half2*)p = __float22half2_rn(make_float2(v.x, v.y));
    *(__half2*)(p + 2) = __float22half2_rn(make_float2(v.z, v.w));
}

// ============ full-K-A GEMM: C[M,Ntot] = A[M,256] @ B^T + bias (fp16 C) ====
// A (fp32 or fp16) staged ONCE (all K=256) into smem; loop N in 256-chunks.
// grid (1, M/128), 512 threads, 16 warps (2m x 8n), warp tile 64x32.
static constexpr int FK_RSTR = 80;                 // bytes / 32k-subtile row
static constexpr int FK_ATILE = 128 * FK_RSTR;     // 10240
static constexpr int FK_A_BYTES = 8 * FK_ATILE;    // 81920
static constexpr int FK_BTILE = 256 * FK_RSTR;     // 20480
static constexpr int FK_SMEM = FK_A_BYTES + 2 * FK_BTILE;   // 122880

template <bool AH, bool RELU>
__global__ __launch_bounds__(512, 1) void gemm_fullA_kernel(
    const void* __restrict__ A_, const float* __restrict__ B,
    const float* __restrict__ bias, __half* __restrict__ C, int Ntot) {
    constexpr int K = 256;
    extern __shared__ char smc[];
    const int tid = threadIdx.x;
    const int lane = tid & 31;
    const int warp = tid >> 5;
    const int wm = warp & 1;
    const int wn = warp >> 1;
    const int m0 = blockIdx.y * 128;
    const uint32_t sbase = smem_u32(smc);
    const int ar = tid >> 3, ac = tid & 7;
    const int g = lane >> 3, r8 = lane & 7;
    const uint32_t a_l = (uint32_t)((wm * 64 + (g & 1) * 8 + r8) * FK_RSTR +
                                    (g >> 1) * 16);
    const uint32_t b_l = (uint32_t)((wn * 32 + (g & 1) * 8 + r8) * FK_RSTR +
                                    (g >> 1) * 16) + FK_A_BYTES;

    // ---- stage full A (8 k-chunks) ----
#pragma unroll
    for (int k0i = 0; k0i < 8; k0i++) {
        char* At = smc + k0i * FK_ATILE;
#pragma unroll
        for (int i = 0; i < 2; i++) {
            int row = ar + i * 64;
            uint2* p = (uint2*)(At + row * FK_RSTR + ac * 8);
            if (AH) {
                *p = *(const uint2*)((const __half*)A_ + (size_t)(m0 + row) * K +
                                     k0i * 32 + ac * 4);
            } else {
                float4 a = *(const float4*)((const float*)A_ +
                                            (size_t)(m0 + row) * K + k0i * 32 + ac * 4);
                *p = make_uint2(pack_h2(a.x, a.y), pack_h2(a.z, a.w));
            }
        }
    }

    const int T = (Ntot >> 8) * 8;   // nc chunks * 8 k-iters
    float4 pb[4];

#define FLDGB(t)                                                                   \
    do {                                                                           \
        int nc_ = (t) >> 3, k0_ = (t) & 7;                                         \
        const float* Bg = B + (size_t)(nc_ * 256) * K + k0_ * 32;                  \
        _Pragma("unroll")                                                          \
        for (int i = 0; i < 4; i++)                                                \
            pb[i] = *(const float4*)&Bg[(size_t)(ar + i * 64) * K + ac * 4];       \
    } while (0)

#define FSTSB(buf)                                                                 \
    do {                                                                           \
        char* Bb_ = smc + FK_A_BYTES + (buf) * FK_BTILE;                           \
        _Pragma("unroll")                                                          \
        for (int i = 0; i < 4; i++) {                                              \
            uint2* p = (uint2*)(Bb_ + (ar + i * 64) * FK_RSTR + ac * 8);           \
            *p = make_uint2(pack_h2(pb[i].x, pb[i].y), pack_h2(pb[i].z, pb[i].w)); \
        }                                                                          \
    } while (0)

    float acc[4][4][4];
#pragma unroll
    for (int i = 0; i < 4; i++)
#pragma unroll
        for (int j = 0; j < 4; j++)
#pragma unroll
            for (int q = 0; q < 4; q++) acc[i][j][q] = 0.f;

    FLDGB(0);
    FSTSB(0);
    __syncthreads();   // also covers A staging
    if (T > 1) FLDGB(1);

    for (int t = 0; t < T; t++) {
        if (t + 1 < T) FSTSB((t + 1) & 1);
        if (t + 2 < T) FLDGB(t + 2);

        const uint32_t aaddr = sbase + (uint32_t)((t & 7) * FK_ATILE) + a_l;
        const uint32_t baddr = sbase + (uint32_t)((t & 1) * FK_BTILE) + b_l;
#pragma unroll
        for (int ks = 0; ks < 2; ks++) {
            uint32_t a[4][4];
#pragma unroll
            for (int i = 0; i < 4; i++)
                ldsm_x4(a[i], aaddr + (uint32_t)(i * 16 * FK_RSTR + ks * 32));
            uint32_t b[4][2];
#pragma unroll
            for (int jj = 0; jj < 2; jj++) {
                uint32_t tt[4];
                ldsm_x4(tt, baddr + (uint32_t)(jj * 16 * FK_RSTR + ks * 32));
                b[2 * jj][0] = tt[0]; b[2 * jj][1] = tt[2];
                b[2 * jj + 1][0] = tt[1]; b[2 * jj + 1][1] = tt[3];
            }
#pragma unroll
            for (int i = 0; i < 4; i++)
#pragma unroll
                for (int j = 0; j < 4; j++) mma_f16(acc[i][j], a[i], b[j]);
        }
        __syncthreads();

        if ((t & 7) == 7) {
            const int n0 = (t >> 3) * 256;
#pragma unroll
            for (int i = 0; i < 4; i++) {
                int mr = m0 + wm * 64 + i * 16 + (lane >> 2);
#pragma unroll
                for (int j = 0; j < 4; j++) {
                    int nc = n0 + wn * 32 + j * 8 + (lane & 3) * 2;
                    float b0 = bias[nc], b1 = bias[nc + 1];
                    float v0 = acc[i][j][0] + b0;
                    float v1 = acc[i][j][1] + b1;
                    float v2 = acc[i][j][2] + b0;
                    float v3 = acc[i][j][3] + b1;
                    if (RELU) {
                        v0 = fmaxf(v0, 0.f); v1 = fmaxf(v1, 0.f);
                        v2 = fmaxf(v2, 0.f); v3 = fmaxf(v3, 0.f);
                    }
                    *(__half2*)&C[(size_t)mr * Ntot + nc] =
                        __float22half2_rn(make_float2(v0, v1));
                    *(__half2*)&C[(size_t)(mr + 8) * Ntot + nc] =
                        __float22half2_rn(make_float2(v2, v3));
                    acc[i][j][0] = 0.f; acc[i][j][1] = 0.f;
                    acc[i][j][2] = 0.f; acc[i][j][3] = 0.f;
                }
            }
        }
    }
#undef FLDGB
#undef FSTSB
}

// ---------------- generic fp16 GEMM (kept for K=512 / LSTM) ---------------
static constexpr int GEMM_RSTRIDE_B = 80;
static constexpr int GEMM_A_BYTES = 128 * GEMM_RSTRIDE_B;
static constexpr int GEMM_B_BYTES = 256 * GEMM_RSTRIDE_B;
static constexpr int GEMM_BUF_BYTES = GEMM_A_BYTES + GEMM_B_BYTES;
static constexpr int GEMM_SMEM = 2 * GEMM_BUF_BYTES;
static constexpr int GEMM_TPB = 512;

template <bool RELU, bool AH, bool CH>
__global__ __launch_bounds__(GEMM_TPB, 1) void mma_gemm_kernel(
    const void* __restrict__ A_, const float* __restrict__ B,
    const float* __restrict__ bias, void* __restrict__ C_,
    int M, int N, int K) {
    extern __shared__ char smc[];
    const int tid = threadIdx.x;
    const int lane = tid & 31;
    const int warp = tid >> 5;
    const int wm = warp & 1;
    const int wn = warp >> 1;
    const int m0 = blockIdx.y * 128;
    const int n0 = blockIdx.x * 256;
    const uint32_t sbase = smem_u32(smc);
    const int ar = tid >> 3, ac = tid & 7;
    const int g = lane >> 3, r8 = lane & 7;
    const uint32_t a_l = (uint32_t)((wm * 64 + (g & 1) * 8 + r8) * GEMM_RSTRIDE_B +
                                    (g >> 1) * 16);
    const uint32_t b_l = (uint32_t)((wn * 32 + (g & 1) * 8 + r8) * GEMM_RSTRIDE_B +
                                    (g >> 1) * 16) + GEMM_A_BYTES;

    float acc[4][4][4];
#pragma unroll
    for (int i = 0; i < 4; i++)
#pragma unroll
        for (int j = 0; j < 4; j++)
#pragma unroll
            for (int q = 0; q < 4; q++) acc[i][j][q] = 0.f;

    const int niter = K >> 5;
    float4 pa[2], pb[4];
    uint2 pa16[2];

#define LDG_TILE(k0i)                                                              \
    do {                                                                           \
        const float* Bg = B + (size_t)n0 * K + (k0i) * 32;                         \
        if (AH) {                                                                  \
            const __half* Ag = (const __half*)A_ + (size_t)m0 * K + (k0i) * 32;    \
            _Pragma("unroll")                                                      \
            for (int i = 0; i < 2; i++)                                            \
                pa16[i] = *(const uint2*)&Ag[(size_t)(ar + i * 64) * K + ac * 4];  \
        } else {                                                                   \
            const float* Ag = (const float*)A_ + (size_t)m0 * K + (k0i) * 32;      \
            _Pragma("unroll")                                                      \
            for (int i = 0; i < 2; i++)                                            \
                pa[i] = *(const float4*)&Ag[(size_t)(ar + i * 64) * K + ac * 4];   \
        }                                                                          \
        _Pragma("unroll")                                                          \
        for (int i = 0; i < 4; i++)                                                \
            pb[i] = *(const float4*)&Bg[(size_t)(ar + i * 64) * K + ac * 4];       \
    } while (0)

#define STS_TILE(buf)                                                              \
    do {                                                                           \
        char* Ab_ = smc + (buf) * GEMM_BUF_BYTES;                                  \
        char* Bb_ = Ab_ + GEMM_A_BYTES;                                            \
        _Pragma("unroll")                                                          \
        for (int i = 0; i < 2; i++) {                                              \
            uint2* p = (uint2*)(Ab_ + (ar + i * 64) * GEMM_RSTRIDE_B + ac * 8);    \
            if (AH) *p = pa16[i];                                                  \
            else                                                                   \
                *p = make_uint2(pack_h2(pa[i].x, pa[i].y),                         \
                                pack_h2(pa[i].z, pa[i].w));                        \
        }                                                                          \
        _Pragma("unroll")                                                          \
        for (int i = 0; i < 4; i++) {                                              \
            uint2* p = (uint2*)(Bb_ + (ar + i * 64) * GEMM_RSTRIDE_B + ac * 8);    \
            *p = make_uint2(pack_h2(pb[i].x, pb[i].y), pack_h2(pb[i].z, pb[i].w)); \
        }                                                                          \
    } while (0)

    LDG_TILE(0);
    STS_TILE(0);
    __syncthreads();
    if (niter > 1) LDG_TILE(1);

    for (int k0i = 0; k0i < niter; k0i++) {
        if (k0i + 1 < niter) STS_TILE((k0i + 1) & 1);
        if (k0i + 2 < niter) LDG_TILE(k0i + 2);

        const uint32_t base = sbase + (uint32_t)((k0i & 1) * GEMM_BUF_BYTES);
        const uint32_t aaddr = base + a_l;
        const uint32_t baddr = base + b_l;
#pragma unroll
        for (int ks = 0; ks < 2; ks++) {
            uint32_t a[4][4];
#pragma unroll
            for (int i = 0; i < 4; i++)
                ldsm_x4(a[i], aaddr + (uint32_t)(i * 16 * GEMM_RSTRIDE_B + ks * 32));
            uint32_t b[4][2];
#pragma unroll
            for (int jj = 0; jj < 2; jj++) {
                uint32_t t[4];
                ldsm_x4(t, baddr + (uint32_t)(jj * 16 * GEMM_RSTRIDE_B + ks * 32));
                b[2 * jj][0] = t[0]; b[2 * jj][1] = t[2];
                b[2 * jj + 1][0] = t[1]; b[2 * jj + 1][1] = t[3];
            }
#pragma unroll
            for (int i = 0; i < 4; i++)
#pragma unroll
                for (int j = 0; j < 4; j++) mma_f16(acc[i][j], a[i], b[j]);
        }
        __syncthreads();
    }

#pragma unroll
    for (int i = 0; i < 4; i++) {
        int mr = m0 + wm * 64 + i * 16 + (lane >> 2);
#pragma unroll
        for (int j = 0; j < 4; j++) {
            int nc = n0 + wn * 32 + j * 8 + (lane & 3) * 2;
            float b0 = bias[nc], b1 = bias[nc + 1];
            float v0 = acc[i][j][0] + b0;
            float v1 = acc[i][j][1] + b1;
            float v2 = acc[i][j][2] + b0;
            float v3 = acc[i][j][3] + b1;
            if (RELU) {
                v0 = fmaxf(v0, 0.f); v1 = fmaxf(v1, 0.f);
                v2 = fmaxf(v2, 0.f); v3 = fmaxf(v3, 0.f);
            }
            if (CH) {
                __half* C = (__half*)C_;
                *(__half2*)&C[(size_t)mr * N + nc] =
                    __float22half2_rn(make_float2(v0, v1));
                *(__half2*)&C[(size_t)(mr + 8) * N + nc] =
                    __float22half2_rn(make_float2(v2, v3));
            } else {
                float* C = (float*)C_;
                *(float2*)&C[(size_t)mr * N + nc] = make_float2(v0, v1);
                *(float2*)&C[(size_t)(mr + 8) * N + nc] = make_float2(v2, v3);
            }
        }
    }
#undef LDG_TILE
#undef STS_TILE
}

// ---------------- CSR build (parallel 3-phase scan) ----------------
__global__ void csr_count_kernel(const int* __restrict__ ei, int* __restrict__ count) {
    int e = (int)((size_t)blockIdx.x * blockDim.x + threadIdx.x);
    if (e >= N_EDGES) return;
    atomicAdd(&count[ei[N_EDGES + e]], 1);
}

__global__ void csr_scan1_kernel(const int* __restrict__ count,
                                 int* __restrict__ rowstart,
                                 int* __restrict__ blocksum) {
    __shared__ int ts[256];
    const int t = threadIdx.x;
    const int base = blockIdx.x * 1024 + t * 4;
    int c0 = count[base], c1 = count[base + 1], c2 = count[base + 2], c3 = count[base + 3];
    int local = c0 + c1 + c2 + c3;
    ts[t] = local;
    __syncthreads();
#pragma unroll
    for (int off = 1; off < 256; off <<= 1) {
        int v = (t >= off) ? ts[t - off] : 0;
        __syncthreads();
        ts[t] += v;
        __syncthreads();
    }
    int pre = ts[t] - local;
    rowstart[base] = pre;
    rowstart[base + 1] = pre + c0;
    rowstart[base + 2] = pre + c0 + c1;
    rowstart[base + 3] = pre + c0 + c1 + c2;
    if (t == 255) blocksum[blockIdx.x] = ts[255];
}

__global__ void csr_scan2_kernel(int* __restrict__ blocksum) {
    __shared__ int ts[128];
    const int t = threadIdx.x;
    int v0 = blocksum[t];
    ts[t] = v0;
    __syncthreads();
#pragma unroll
    for (int off = 1; off < 128; off <<= 1) {
        int v = (t >= off) ? ts[t - off] : 0;
        __syncthreads();
        ts[t] += v;
        __syncthreads();
    }
    blocksum[t] = ts[t] - v0;
}

__global__ void csr_scan3_kernel(int* __restrict__ rowstart, int* __restrict__ cursor,
                                 const int* __restrict__ blocksum) {
    const int i = blockIdx.x * 1024 + threadIdx.x * 4;
    const int off = blocksum[blockIdx.x];
#pragma unroll
    for (int q = 0; q < 4; q++) {
        int v = rowstart[i + q] + off;
        rowstart[i + q] = v;
        cursor[i + q] = v;
    }
    if (blockIdx.x == 0 && threadIdx.x == 0) rowstart[N_NODES] = N_EDGES;
}

__global__ void csr_fill_kernel(const int* __restrict__ ei, int* __restrict__ cursor,
                                int* __restrict__ csr_src, int* __restrict__ csr_eid) {
    int e = (int)((size_t)blockIdx.x * blockDim.x + threadIdx.x);
    if (e >= N_EDGES) return;
    int d = ei[N_EDGES + e];
    int pos = atomicAdd(&cursor[d], 1);
    csr_src[pos] = ei[e];
    csr_eid[pos] = e;
}

// ---------------- edge gather: agg16[n] = x[n] + sum relu(x[src] + e) ------
__global__ void edge_gather_kernel(const int* __restrict__ rowstart,
                                   const int* __restrict__ csr_src,
                                   const int* __restrict__ csr_eid,
                                   const float* __restrict__ x,
                                   const __half* __restrict__ e,
                                   __half* __restrict__ agg) {
    size_t idx = (size_t)blockIdx.x * blockDim.x + threadIdx.x;
    if (idx >= (size_t)N_NODES * 64) return;
    int n = (int)(idx >> 6);
    int c = (int)(idx & 63);
    int beg = rowstart[n], end = rowstart[n + 1];
    float4 acc = *(const float4*)&x[(size_t)n * D + c * 4];
    for (int k = beg; k < end; k++) {
        int s = csr_src[k];
        int eid = csr_eid[k];
        float4 xv = *(const float4*)&x[(size_t)s * D + c * 4];
        float ev[4];
        ld4h(e + (size_t)eid * D + c * 4, ev);
        acc.x += fmaxf(xv.x + ev[0], 0.f);
        acc.y += fmaxf(xv.y + ev[1], 0.f);
        acc.z += fmaxf(xv.z + ev[2], 0.f);
        acc.w += fmaxf(xv.w + ev[3], 0.f);
    }
    st4h(agg + (size_t)n * D + c * 4, acc);
}

// ---------------- weight transpose ----------------
__global__ void transpose_kernel(const float* __restrict__ in, float* __restrict__ out,
                                 int R, int C) {
    __shared__ float t[32][33];
    int c0 = blockIdx.x * 32, r0 = blockIdx.y * 32;
    for (int i = threadIdx.y; i < 32; i += 8)
        t[i][threadIdx.x] = in[(size_t)(r0 + i) * C + c0 + threadIdx.x];
    __syncthreads();
    for (int i = threadIdx.y; i < 32; i += 8)
        out[(size_t)(c0 + i) * R + r0 + threadIdx.x] = t[threadIdx.x][i];
}

// ---------------- encoders ----------------
__global__ void atom_encode_kernel(const int* __restrict__ xa,
                                   const float* __restrict__ emb,
                                   float* __restrict__ hx0, float* __restrict__ hx1) {
    size_t idx = (size_t)blockIdx.x * blockDim.x + threadIdx.x;
    if (idx >= (size_t)N_NODES * 64) return;
    int n = (int)(idx >> 6);
    int c = (int)(idx & 63);
    float4 acc = make_float4(0.f, 0.f, 0.f, 0.f);
#pragma unroll
    for (int i = 0; i < 9; i++) {
        int t = xa[n * 9 + i];
        const float4 v = *(const float4*)&emb[((size_t)(i * 120 + t)) * D + c * 4];
        acc.x += v.x; acc.y += v.y; acc.z += v.z; acc.w += v.w;
    }
    size_t o = (size_t)n * D + c * 4;
    *(float4*)&hx0[o] = acc;
    *(float4*)&hx1[o] = acc;
}

__global__ void bond_encode_kernel(const int* __restrict__ ea,
                                   const float* __restrict__ emb,
                                   __half* __restrict__ e_out) {
    __shared__ float tab[3 * 6 * D];
    for (int i = threadIdx.x; i < 3 * 6 * D; i += blockDim.x) tab[i] = emb[i];
    __syncthreads();
    size_t total = (size_t)N_EDGES * 64;
    size_t stride = (size_t)gridDim.x * blockDim.x;
    for (size_t idx = (size_t)blockIdx.x * blockDim.x + threadIdx.x; idx < total;
         idx += stride) {
        int n = (int)(idx >> 6);
        int c = (int)(idx & 63);
        float4 acc = make_float4(0.f, 0.f, 0.f, 0.f);
#pragma unroll
        for (int i = 0; i < 3; i++) {
            int t = ea[n * 3 + i];
            const float4 v = *(const float4*)&tab[(i * 6 + t) * D + c * 4];
            acc.x += v.x; acc.y += v.y; acc.z += v.z; acc.w += v.w;
        }
        st4h(e_out + (size_t)n * D + c * 4, acc);
    }
}

// ---------------- GRU / LSTM gates ----------------
__global__ void gru_gate_kernel(const __half* __restrict__ gi,
                                const __half* __restrict__ gh,
                                float* __restrict__ hx) {
    size_t idx = (size_t)blockIdx.x * blockDim.x + threadIdx.x;
    if (idx >= (size_t)N_NODES * 64) return;
    int n = (int)(idx >> 6);
    int c = (int)(idx & 63);
    size_t base = (size_t)n * 3 * D + c * 4;
    float ir[4], iz[4], in_[4], hr[4], hz[4], hn[4];
    ld4h(gi + base, ir); ld4h(gi + base + D, iz); ld4h(gi + base + 2 * D, in_);
    ld4h(gh + base, hr); ld4h(gh + base + D, hz); ld4h(gh + base + 2 * D, hn);
    size_t hidx = (size_t)n * D + c * 4;
    float4 hp = *(const float4*)&hx[hidx];
    float hpv[4] = {hp.x, hp.y, hp.z, hp.w};
    float ov[4];
#pragma unroll
    for (int q = 0; q < 4; q++) {
        float r = sigmoidf_(ir[q] + hr[q]);
        float z = sigmoidf_(iz[q] + hz[q]);
        float nn = tanhf(in_[q] + r * hn[q]);
        ov[q] = (1.0f - z) * nn + z * hpv[q];
    }
    *(float4*)&hx[hidx] = make_float4(ov[0], ov[1], ov[2], ov[3]);
}

__global__ void lstm_gate_kernel(const float* __restrict__ g1,
                                 const float* __restrict__ g2,
                                 float* __restrict__ hs, float* __restrict__ cs) {
    size_t idx = (size_t)blockIdx.x * blockDim.x + threadIdx.x;
    if (idx >= (size_t)N_GRAPHS * D) return;
    int b = (int)(idx >> 8);
    int d = (int)(idx & 255);
    size_t base = (size_t)b * 4 * D + d;
    float ig = sigmoidf_(g1[base] + g2[base]);
    float fg = sigmoidf_(g1[base + D] + g2[base + D]);
    float gg = tanhf(g1[base + 2 * D] + g2[base + 2 * D]);
    float og = sigmoidf_(g1[base + 3 * D] + g2[base + 3 * D]);
    float c = fg * cs[idx] + ig * gg;
    cs[idx] = c;
    hs[idx] = og * tanhf(c);
}

// ---------------- Set2Set attention ----------------
__global__ void s2s_prep_kernel(float* __restrict__ qstar,
                                const float* __restrict__ hs,
                                float* __restrict__ m, float* __restrict__ norm) {
    size_t i = (size_t)blockIdx.x * blockDim.x + threadIdx.x;
    if (i < N_GRAPHS) { m[i] = -INFINITY; norm[i] = 0.f; }
    if (i < (size_t)N_GRAPHS * D) {
        int b = (int)(i >> 8);
        int d = (int)(i & 255);
        qstar[(size_t)b * 2 * D + d] = hs[i];
        qstar[(size_t)b * 2 * D + D + d] = 0.f;
    }
}

__global__ void attn_prod_kernel(const float* __restrict__ hs,
                                 const float* __restrict__ x,
                                 const int* __restrict__ batch,
                                 float* __restrict__ prod) {
    int warp = (int)(((size_t)blockIdx.x * blockDim.x + threadIdx.x) >> 5);
    int lane = threadIdx.x & 31;
    if (warp >= N_NODES) return;
    int b = batch[warp];
    const float* q = hs + (size_t)b * D;
    const float* xv = x + (size_t)warp * D;
    float s = 0.f;
#pragma unroll
    for (int j = 0; j < D / 32; j++) s += q[lane + j * 32] * xv[lane + j * 32];
#pragma unroll
    for (int o = 16; o; o >>= 1) s += __shfl_xor_sync(0xFFFFFFFFu, s, o);
    if (lane == 0) prod[warp] = s;
}

__global__ void attn_max_kernel(const int* __restrict__ batch,
                                const float* __restrict__ prod,
                                float* __restrict__ m) {
    int n = (int)((size_t)blockIdx.x * blockDim.x + threadIdx.x);
    if (n >= N_NODES) return;
    atomicMaxFloat(&m[batch[n]], prod[n]);
}

__global__ void attn_expnorm_kernel(const int* __restrict__ batch,
                                    float* __restrict__ prod,
                                    const float* __restrict__ m,
                                    float* __restrict__ norm) {
    int n = (int)((size_t)blockIdx.x * blockDim.x + threadIdx.x);
    if (n >= N_NODES) return;
    int b = batch[n];
    float a = expf(prod[n] - m[b]);
    prod[n] = a;
    atomicAdd(&norm[b], a);
}

__global__ void attn_scatter_kernel(const int* __restrict__ batch,
                                    const float* __restrict__ prod,
                                    const float* __restrict__ norm,
                                    const float* __restrict__ x,
                                    float* __restrict__ qstar) {
    size_t idx = (size_t)blockIdx.x * blockDim.x + threadIdx.x;
    if (idx >= (size_t)N_NODES * 64) return;
    int n = (int)(idx >> 6);
    int c = (int)(idx & 63);
    int b = batch[n];
    float coef = prod[n] / (norm[b] + EPS);
    float4 xv = *(const float4*)&x[(size_t)n * D + c * 4];
    float4 v = make_float4(coef * xv.x, coef * xv.y, coef * xv.z, coef * xv.w);
    atomicAdd((float4*)&qstar[(size_t)b * 2 * D + D + c * 4], v);
}

__global__ void fc_kernel(const float* __restrict__ qstar,
                          const float* __restrict__ fw,
                          const float* __restrict__ fb,
                          float* __restrict__ out) {
    int warp = (int)(((size_t)blockIdx.x * blockDim.x + threadIdx.x) >> 5);
    int lane = threadIdx.x & 31;
    if (warp >= N_GRAPHS) return;
    float s = 0.f;
#pragma unroll
    for (int j = 0; j < (2 * D) / 32; j++)
        s += qstar[(size_t)warp * 2 * D + lane + j * 32] * fw[lane + j * 32];
#pragma unroll
    for (int o = 16; o; o >>= 1) s += __shfl_xor_sync(0xFFFFFFFFu, s, o);
    if (lane == 0) out[warp] = s + fb[0];
}

// ---------------- launch ----------------
extern "C" void kernel_launch(void* const* d_in, const int* in_sizes, int n_in,
                              void* d_out, int out_size) {
    const int* x_atoms = (const int*)d_in[0];
    const int* edge_index = (const int*)d_in[1];
    const int* edge_attr = (const int*)d_in[2];
    const int* batch = (const int*)d_in[3];
    const float* atom_emb = (const float*)d_in[4];
    const float* bond_emb = (const float*)d_in[5];
    const float* gin_w1 = (const float*)d_in[6];
    const float* gin_b1 = (const float*)d_in[7];
    const float* gin_w2 = (const float*)d_in[8];
    const float* gin_b2 = (const float*)d_in[9];
    const float* gru_wih = (const float*)d_in[10];
    const float* gru_whh = (const float*)d_in[11];
    const float* gru_bih = (const float*)d_in[12];
    const float* gru_bhh = (const float*)d_in[13];
    const float* lstm_wih = (const float*)d_in[14];
    const float* lstm_whh = (const float*)d_in[15];
    const float* lstm_bih = (const float*)d_in[16];
    const float* lstm_bhh = (const float*)d_in[17];
    const float* fc_w = (const float*)d_in[18];
    const float* fc_b = (const float*)d_in[19];
    float* out = (float*)d_out;

    float *hx0, *hx1, *g1, *g2, *hs, *cs, *qstar, *prod, *mbuf, *norm, *w1t, *w2t;
    __half *e16, *agg16, *t16, *xconv16, *gi16, *gh16;
    int *count, *rowstart, *cursor, *csr_src, *csr_eid, *blocksum;
    cudaGetSymbolAddress((void**)&hx0, g_hx0);
    cudaGetSymbolAddress((void**)&hx1, g_hx1);
    cudaGetSymbolAddress((void**)&e16, g_e16);
    cudaGetSymbolAddress((void**)&agg16, g_agg16);
    cudaGetSymbolAddress((void**)&t16, g_t16);
    cudaGetSymbolAddress((void**)&xconv16, g_xconv16);
    cudaGetSymbolAddress((void**)&gi16, g_gi16);
    cudaGetSymbolAddress((void**)&gh16, g_gh16);
    cudaGetSymbolAddress((void**)&g1, g_g1);
    cudaGetSymbolAddress((void**)&g2, g_g2);
    cudaGetSymbolAddress((void**)&hs, g_hs);
    cudaGetSymbolAddress((void**)&cs, g_cs);
    cudaGetSymbolAddress((void**)&qstar, g_qstar);
    cudaGetSymbolAddress((void**)&prod, g_prod);
    cudaGetSymbolAddress((void**)&mbuf, g_m);
    cudaGetSymbolAddress((void**)&norm, g_norm);
    cudaGetSymbolAddress((void**)&w1t, g_w1t);
    cudaGetSymbolAddress((void**)&w2t, g_w2t);
    cudaGetSymbolAddress((void**)&count, g_count);
    cudaGetSymbolAddress((void**)&rowstart, g_rowstart);
    cudaGetSymbolAddress((void**)&cursor, g_cursor);
    cudaGetSymbolAddress((void**)&csr_src, g_csr_src);
    cudaGetSymbolAddress((void**)&csr_eid, g_csr_eid);
    cudaGetSymbolAddress((void**)&blocksum, g_blocksum);

    cudaFuncSetAttribute(gemm_fullA_kernel<true, true>,
                         cudaFuncAttributeMaxDynamicSharedMemorySize, FK_SMEM);
    cudaFuncSetAttribute(gemm_fullA_kernel<true, false>,
                         cudaFuncAttributeMaxDynamicSharedMemorySize, FK_SMEM);
    cudaFuncSetAttribute(gemm_fullA_kernel<false, false>,
                         cudaFuncAttributeMaxDynamicSharedMemorySize, FK_SMEM);
    cudaFuncSetAttribute(mma_gemm_kernel<false, true, true>,
                         cudaFuncAttributeMaxDynamicSharedMemorySize, GEMM_SMEM);
    cudaFuncSetAttribute(mma_gemm_kernel<false, false, false>,
                         cudaFuncAttributeMaxDynamicSharedMemorySize, GEMM_SMEM);

    const int TPB = 256;

    transpose_kernel<<<dim3(512 / 32, 256 / 32), dim3(32, 8)>>>(gin_w1, w1t, 256, 512);
    transpose_kernel<<<dim3(256 / 32, 512 / 32), dim3(32, 8)>>>(gin_w2, w2t, 512, 256);

    cudaMemsetAsync(count, 0, N_NODES * sizeof(int));
    csr_count_kernel<<<N_EDGES / TPB, TPB>>>(edge_index, count);
    csr_scan1_kernel<<<128, 256>>>(count, rowstart, blocksum);
    csr_scan2_kernel<<<1, 128>>>(blocksum);
    csr_scan3_kernel<<<128, 256>>>(rowstart, cursor, blocksum);
    csr_fill_kernel<<<N_EDGES / TPB, TPB>>>(edge_index, cursor, csr_src, csr_eid);

    atom_encode_kernel<<<(N_NODES * 64) / TPB, TPB>>>(x_atoms, atom_emb, hx0, hx1);
    bond_encode_kernel<<<2048, TPB>>>(edge_attr, bond_emb, e16);
    cudaMemsetAsync(hs, 0, (size_t)N_GRAPHS * D * sizeof(float));
    cudaMemsetAsync(cs, 0, (size_t)N_GRAPHS * D * sizeof(float));
    cudaMemsetAsync(qstar, 0, (size_t)N_GRAPHS * 2 * D * sizeof(float));

    const dim3 fkgrid(1, N_NODES / 128);
    for (int layer = 0; layer < 3; layer++) {
        edge_gather_kernel<<<(N_NODES * 64) / TPB, TPB>>>(rowstart, csr_src, csr_eid,
                                                          hx1, e16, agg16);
        // GIN MLP: agg16 -> t16 (relu) -> xconv16
        gemm_fullA_kernel<true, true><<<fkgrid, 512, FK_SMEM>>>(
            agg16, w1t, gin_b1, t16, 512);
        mma_gemm_kernel<false, true, true>
            <<<dim3(1, N_NODES / 128), GEMM_TPB, GEMM_SMEM>>>(
                t16, w2t, gin_b2, xconv16, N_NODES, 256, 512);
        // GRU layer 0
        gemm_fullA_kernel<true, false><<<fkgrid, 512, FK_SMEM>>>(
            xconv16, gru_wih, gru_bih, gi16, 768);
        gemm_fullA_kernel<false, false><<<fkgrid, 512, FK_SMEM>>>(
            hx0, gru_whh, gru_bhh, gh16, 768);
        gru_gate_kernel<<<(N_NODES * 64) / TPB, TPB>>>(gi16, gh16, hx0);
        // GRU layer 1
        gemm_fullA_kernel<false, false><<<fkgrid, 512, FK_SMEM>>>(
            hx0, gru_wih + 768 * 256, gru_bih + 768, gi16, 768);
        gemm_fullA_kernel<false, false><<<fkgrid, 512, FK_SMEM>>>(
            hx1, gru_whh + 768 * 256, gru_bhh + 768, gh16, 768);
        gru_gate_kernel<<<(N_NODES * 64) / TPB, TPB>>>(gi16, gh16, hx1);
    }

    for (int step = 0; step < 3; step++) {
        mma_gemm_kernel<false, false, false>
            <<<dim3(1024 / 256, N_GRAPHS / 128), GEMM_TPB, GEMM_SMEM>>>(
                qstar, lstm_wih, lstm_bih, g1, N_GRAPHS, 1024, 512);
        mma_gemm_kernel<false, false, false>
            <<<dim3(1024 / 256, N_GRAPHS / 128), GEMM_TPB, GEMM_SMEM>>>(
                hs, lstm_whh, lstm_bhh, g2, N_GRAPHS, 1024, 256);
        lstm_gate_kernel<<<(N_GRAPHS * D) / TPB, TPB>>>(g1, g2, hs, cs);
        s2s_prep_kernel<<<(N_GRAPHS * D) / TPB, TPB>>>(qstar, hs, mbuf, norm);
        attn_prod_kernel<<<(N_NODES * 32) / TPB, TPB>>>(hs, hx1, batch, prod);
        attn_max_kernel<<<N_NODES / TPB, TPB>>>(batch, prod, mbuf);
        attn_expnorm_kernel<<<N_NODES / TPB, TPB>>>(batch, prod, mbuf, norm);
        attn_scatter_kernel<<<(N_NODES * 64) / TPB, TPB>>>(batch, prod, norm, hx1, qstar);
    }

    fc_kernel<<<(N_GRAPHS * 32) / TPB, TPB>>>(qstar, fc_w, fc_b, out);
}

// round 15
// speedup vs baseline: 1.2020x; 1.0287x over previous
#include <cuda_runtime.h>
#include <cuda_bf16.h>
#include <cuda_fp16.h>
#include <math.h>
#include <stdint.h>

#define N_NODES 131072
#define N_EDGES 524288
#define N_GRAPHS 4096
#define D 256
#define EPS 1e-10f

// ---------------- scratch (device globals; no allocation allowed) ----------
__device__ float g_hx0[N_NODES * D];
__device__ float g_hx1[N_NODES * D];          // aliases x
__device__ __half g_e16[N_EDGES * D];
__device__ __half g_agg16[N_NODES * D];
__device__ __half g_t16[N_NODES * 2 * D];
__device__ __half g_xconv16[N_NODES * D];
__device__ __half g_gi16[N_NODES * 3 * D];
__device__ __half g_gh16[N_NODES * 3 * D];
__device__ float g_g1[N_GRAPHS * 4 * D];
__device__ float g_g2[N_GRAPHS * 4 * D];
__device__ float g_hs[N_GRAPHS * D];
__device__ float g_cs[N_GRAPHS * D];
__device__ float g_qstar[N_GRAPHS * 2 * D];
__device__ float g_prod[N_NODES];
__device__ float g_w1t[512 * 256];
__device__ float g_w2t[256 * 512];
// CSR (built once per call)
__device__ int g_count[N_NODES];
__device__ int g_rowstart[N_NODES + 1];
__device__ int g_cursor[N_NODES];
__device__ int g_csr_src[N_EDGES];
__device__ int g_csr_eid[N_EDGES];
__device__ int g_blocksum[128];
__device__ int g_gbstart[N_GRAPHS + 1];

// ---------------- helpers ----------------
__device__ __forceinline__ uint32_t smem_u32(const void* p) {
    uint32_t a;
    asm("{ .reg .u64 t; cvta.to.shared.u64 t, %1; cvt.u32.u64 %0, t; }" : "=r"(a) : "l"(p));
    return a;
}
__device__ __forceinline__ float sigmoidf_(float x) { return 1.0f / (1.0f + expf(-x)); }
__device__ __forceinline__ void mma_f16(float* c, const uint32_t* a, const uint32_t* b) {
    asm volatile(
        "mma.sync.aligned.m16n8k16.row.col.f32.f16.f16.f32 "
        "{%0,%1,%2,%3}, {%4,%5,%6,%7}, {%8,%9}, {%0,%1,%2,%3};"
        : "+f"(c[0]), "+f"(c[1]), "+f"(c[2]), "+f"(c[3])
        : "r"(a[0]), "r"(a[1]), "r"(a[2]), "r"(a[3]), "r"(b[0]), "r"(b[1]));
}
__device__ __forceinline__ void ldsm_x4(uint32_t* r, uint32_t saddr) {
    asm volatile("ldmatrix.sync.aligned.m8n8.x4.shared.b16 {%0,%1,%2,%3}, [%4];"
                 : "=r"(r[0]), "=r"(r[1]), "=r"(r[2]), "=r"(r[3]) : "r"(saddr));
}
__device__ __forceinline__ uint32_t pack_h2(float x, float y) {
    __half2 h = __float22half2_rn(make_float2(x, y));
    return *(uint32_t*)&h;
}
__device__ __forceinline__ void ld4h(const __half* p, float* o) {
    __half2 a = *(const __half2*)p;
    __half2 b = *(const __half2*)(p + 2);
    o[0] = __low2float(a); o[1] = __high2float(a);
    o[2] = __low2float(b); o[3] = __high2float(b);
}
__device__ __forceinline__ void st4h(__half* p, float4 v) {
    *(__half2*)p = __float22half2_rn(make_float2(v.x, v.y));
    *(__half2*)(p + 2) = __float22half2_rn(make_float2(v.z, v.w));
}

// ============ full-K-A GEMM: C[M,Ntot] = A[M,256] @ B^T + bias (fp16 C) ====
static constexpr int FK_RSTR = 80;
static constexpr int FK_ATILE = 128 * FK_RSTR;
static constexpr int FK_A_BYTES = 8 * FK_ATILE;
static constexpr int FK_BTILE = 256 * FK_RSTR;
static constexpr int FK_SMEM = FK_A_BYTES + 2 * FK_BTILE;

template <bool AH, bool RELU>
__global__ __launch_bounds__(512, 1) void gemm_fullA_kernel(
    const void* __restrict__ A_, const float* __restrict__ B,
    const float* __restrict__ bias, __half* __restrict__ C, int Ntot) {
    constexpr int K = 256;
    extern __shared__ char smc[];
    const int tid = threadIdx.x;
    const int lane = tid & 31;
    const int warp = tid >> 5;
    const int wm = warp & 1;
    const int wn = warp >> 1;
    const int m0 = blockIdx.y * 128;
    const uint32_t sbase = smem_u32(smc);
    const int ar = tid >> 3, ac = tid & 7;
    const int g = lane >> 3, r8 = lane & 7;
    const uint32_t a_l = (uint32_t)((wm * 64 + (g & 1) * 8 + r8) * FK_RSTR +
                                    (g >> 1) * 16);
    const uint32_t b_l = (uint32_t)((wn * 32 + (g & 1) * 8 + r8) * FK_RSTR +
                                    (g >> 1) * 16) + FK_A_BYTES;

#pragma unroll
    for (int k0i = 0; k0i < 8; k0i++) {
        char* At = smc + k0i * FK_ATILE;
#pragma unroll
        for (int i = 0; i < 2; i++) {
            int row = ar + i * 64;
            uint2* p = (uint2*)(At + row * FK_RSTR + ac * 8);
            if (AH) {
                *p = *(const uint2*)((const __half*)A_ + (size_t)(m0 + row) * K +
                                     k0i * 32 + ac * 4);
            } else {
                float4 a = *(const float4*)((const float*)A_ +
                                            (size_t)(m0 + row) * K + k0i * 32 + ac * 4);
                *p = make_uint2(pack_h2(a.x, a.y), pack_h2(a.z, a.w));
            }
        }
    }

    const int T = (Ntot >> 8) * 8;
    float4 pb[4];

#define FLDGB(t)                                                                   \
    do {                                                                           \
        int nc_ = (t) >> 3, k0_ = (t) & 7;                                         \
        const float* Bg = B + (size_t)(nc_ * 256) * K + k0_ * 32;                  \
        _Pragma("unroll")                                                          \
        for (int i = 0; i < 4; i++)                                                \
            pb[i] = *(const float4*)&Bg[(size_t)(ar + i * 64) * K + ac * 4];       \
    } while (0)

#define FSTSB(buf)                                                                 \
    do {                                                                           \
        char* Bb_ = smc + FK_A_BYTES + (buf) * FK_BTILE;                           \
        _Pragma("unroll")                                                          \
        for (int i = 0; i < 4; i++) {                                              \
            uint2* p = (uint2*)(Bb_ + (ar + i * 64) * FK_RSTR + ac * 8);           \
            *p = make_uint2(pack_h2(pb[i].x, pb[i].y), pack_h2(pb[i].z, pb[i].w)); \
        }                                                                          \
    } while (0)

    float acc[4][4][4];
#pragma unroll
    for (int i = 0; i < 4; i++)
#pragma unroll
        for (int j = 0; j < 4; j++)
#pragma unroll
            for (int q = 0; q < 4; q++) acc[i][j][q] = 0.f;

    FLDGB(0);
    FSTSB(0);
    __syncthreads();
    if (T > 1) FLDGB(1);

    for (int t = 0; t < T; t++) {
        if (t + 1 < T) FSTSB((t + 1) & 1);
        if (t + 2 < T) FLDGB(t + 2);

        const uint32_t aaddr = sbase + (uint32_t)((t & 7) * FK_ATILE) + a_l;
        const uint32_t baddr = sbase + (uint32_t)((t & 1) * FK_BTILE) + b_l;
#pragma unroll
        for (int ks = 0; ks < 2; ks++) {
            uint32_t a[4][4];
#pragma unroll
            for (int i = 0; i < 4; i++)
                ldsm_x4(a[i], aaddr + (uint32_t)(i * 16 * FK_RSTR + ks * 32));
            uint32_t b[4][2];
#pragma unroll
            for (int jj = 0; jj < 2; jj++) {
                uint32_t tt[4];
                ldsm_x4(tt, baddr + (uint32_t)(jj * 16 * FK_RSTR + ks * 32));
                b[2 * jj][0] = tt[0]; b[2 * jj][1] = tt[2];
                b[2 * jj + 1][0] = tt[1]; b[2 * jj + 1][1] = tt[3];
            }
#pragma unroll
            for (int i = 0; i < 4; i++)
#pragma unroll
                for (int j = 0; j < 4; j++) mma_f16(acc[i][j], a[i], b[j]);
        }
        __syncthreads();

        if ((t & 7) == 7) {
            const int n0 = (t >> 3) * 256;
#pragma unroll
            for (int i = 0; i < 4; i++) {
                int mr = m0 + wm * 64 + i * 16 + (lane >> 2);
#pragma unroll
                for (int j = 0; j < 4; j++) {
                    int nc = n0 + wn * 32 + j * 8 + (lane & 3) * 2;
                    float b0 = bias[nc], b1 = bias[nc + 1];
                    float v0 = acc[i][j][0] + b0;
                    float v1 = acc[i][j][1] + b1;
                    float v2 = acc[i][j][2] + b0;
                    float v3 = acc[i][j][3] + b1;
                    if (RELU) {
                        v0 = fmaxf(v0, 0.f); v1 = fmaxf(v1, 0.f);
                        v2 = fmaxf(v2, 0.f); v3 = fmaxf(v3, 0.f);
                    }
                    *(__half2*)&C[(size_t)mr * Ntot + nc] =
                        __float22half2_rn(make_float2(v0, v1));
                    *(__half2*)&C[(size_t)(mr + 8) * Ntot + nc] =
                        __float22half2_rn(make_float2(v2, v3));
                    acc[i][j][0] = 0.f; acc[i][j][1] = 0.f;
                    acc[i][j][2] = 0.f; acc[i][j][3] = 0.f;
                }
            }
        }
    }
#undef FLDGB
#undef FSTSB
}

// ---------------- generic fp16 GEMM (K=512 GIN2 / LSTM) -------------------
static constexpr int GEMM_RSTRIDE_B = 80;
static constexpr int GEMM_A_BYTES = 128 * GEMM_RSTRIDE_B;
static constexpr int GEMM_B_BYTES = 256 * GEMM_RSTRIDE_B;
static constexpr int GEMM_BUF_BYTES = GEMM_A_BYTES + GEMM_B_BYTES;
static constexpr int GEMM_SMEM = 2 * GEMM_BUF_BYTES;
static constexpr int GEMM_TPB = 512;

template <bool RELU, bool AH, bool CH>
__global__ __launch_bounds__(GEMM_TPB, 1) void mma_gemm_kernel(
    const void* __restrict__ A_, const float* __restrict__ B,
    const float* __restrict__ bias, void* __restrict__ C_,
    int M, int N, int K) {
    extern __shared__ char smc[];
    const int tid = threadIdx.x;
    const int lane = tid & 31;
    const int warp = tid >> 5;
    const int wm = warp & 1;
    const int wn = warp >> 1;
    const int m0 = blockIdx.y * 128;
    const int n0 = blockIdx.x * 256;
    const uint32_t sbase = smem_u32(smc);
    const int ar = tid >> 3, ac = tid & 7;
    const int g = lane >> 3, r8 = lane & 7;
    const uint32_t a_l = (uint32_t)((wm * 64 + (g & 1) * 8 + r8) * GEMM_RSTRIDE_B +
                                    (g >> 1) * 16);
    const uint32_t b_l = (uint32_t)((wn * 32 + (g & 1) * 8 + r8) * GEMM_RSTRIDE_B +
                                    (g >> 1) * 16) + GEMM_A_BYTES;

    float acc[4][4][4];
#pragma unroll
    for (int i = 0; i < 4; i++)
#pragma unroll
        for (int j = 0; j < 4; j++)
#pragma unroll
            for (int q = 0; q < 4; q++) acc[i][j][q] = 0.f;

    const int niter = K >> 5;
    float4 pa[2], pb[4];
    uint2 pa16[2];

#define LDG_TILE(k0i)                                                              \
    do {                                                                           \
        const float* Bg = B + (size_t)n0 * K + (k0i) * 32;                         \
        if (AH) {                                                                  \
            const __half* Ag = (const __half*)A_ + (size_t)m0 * K + (k0i) * 32;    \
            _Pragma("unroll")                                                      \
            for (int i = 0; i < 2; i++)                                            \
                pa16[i] = *(const uint2*)&Ag[(size_t)(ar + i * 64) * K + ac * 4];  \
        } else {                                                                   \
            const float* Ag = (const float*)A_ + (size_t)m0 * K + (k0i) * 32;      \
            _Pragma("unroll")                                                      \
            for (int i = 0; i < 2; i++)                                            \
                pa[i] = *(const float4*)&Ag[(size_t)(ar + i * 64) * K + ac * 4];   \
        }                                                                          \
        _Pragma("unroll")                                                          \
        for (int i = 0; i < 4; i++)                                                \
            pb[i] = *(const float4*)&Bg[(size_t)(ar + i * 64) * K + ac * 4];       \
    } while (0)

#define STS_TILE(buf)                                                              \
    do {                                                                           \
        char* Ab_ = smc + (buf) * GEMM_BUF_BYTES;                                  \
        char* Bb_ = Ab_ + GEMM_A_BYTES;                                            \
        _Pragma("unroll")                                                          \
        for (int i = 0; i < 2; i++) {                                              \
            uint2* p = (uint2*)(Ab_ + (ar + i * 64) * GEMM_RSTRIDE_B + ac * 8);    \
            if (AH) *p = pa16[i];                                                  \
            else                                                                   \
                *p = make_uint2(pack_h2(pa[i].x, pa[i].y),                         \
                                pack_h2(pa[i].z, pa[i].w));                        \
        }                                                                          \
        _Pragma("unroll")                                                          \
        for (int i = 0; i < 4; i++) {                                              \
            uint2* p = (uint2*)(Bb_ + (ar + i * 64) * GEMM_RSTRIDE_B + ac * 8);    \
            *p = make_uint2(pack_h2(pb[i].x, pb[i].y), pack_h2(pb[i].z, pb[i].w)); \
        }                                                                          \
    } while (0)

    LDG_TILE(0);
    STS_TILE(0);
    __syncthreads();
    if (niter > 1) LDG_TILE(1);

    for (int k0i = 0; k0i < niter; k0i++) {
        if (k0i + 1 < niter) STS_TILE((k0i + 1) & 1);
        if (k0i + 2 < niter) LDG_TILE(k0i + 2);

        const uint32_t base = sbase + (uint32_t)((k0i & 1) * GEMM_BUF_BYTES);
        const uint32_t aaddr = base + a_l;
        const uint32_t baddr = base + b_l;
#pragma unroll
        for (int ks = 0; ks < 2; ks++) {
            uint32_t a[4][4];
#pragma unroll
            for (int i = 0; i < 4; i++)
                ldsm_x4(a[i], aaddr + (uint32_t)(i * 16 * GEMM_RSTRIDE_B + ks * 32));
            uint32_t b[4][2];
#pragma unroll
            for (int jj = 0; jj < 2; jj++) {
                uint32_t t[4];
                ldsm_x4(t, baddr + (uint32_t)(jj * 16 * GEMM_RSTRIDE_B + ks * 32));
                b[2 * jj][0] = t[0]; b[2 * jj][1] = t[2];
                b[2 * jj + 1][0] = t[1]; b[2 * jj + 1][1] = t[3];
            }
#pragma unroll
            for (int i = 0; i < 4; i++)
#pragma unroll
                for (int j = 0; j < 4; j++) mma_f16(acc[i][j], a[i], b[j]);
        }
        __syncthreads();
    }

#pragma unroll
    for (int i = 0; i < 4; i++) {
        int mr = m0 + wm * 64 + i * 16 + (lane >> 2);
#pragma unroll
        for (int j = 0; j < 4; j++) {
            int nc = n0 + wn * 32 + j * 8 + (lane & 3) * 2;
            float b0 = bias[nc], b1 = bias[nc + 1];
            float v0 = acc[i][j][0] + b0;
            float v1 = acc[i][j][1] + b1;
            float v2 = acc[i][j][2] + b0;
            float v3 = acc[i][j][3] + b1;
            if (RELU) {
                v0 = fmaxf(v0, 0.f); v1 = fmaxf(v1, 0.f);
                v2 = fmaxf(v2, 0.f); v3 = fmaxf(v3, 0.f);
            }
            if (CH) {
                __half* C = (__half*)C_;
                *(__half2*)&C[(size_t)mr * N + nc] =
                    __float22half2_rn(make_float2(v0, v1));
                *(__half2*)&C[(size_t)(mr + 8) * N + nc] =
                    __float22half2_rn(make_float2(v2, v3));
            } else {
                float* C = (float*)C_;
                *(float2*)&C[(size_t)mr * N + nc] = make_float2(v0, v1);
                *(float2*)&C[(size_t)(mr + 8) * N + nc] = make_float2(v2, v3);
            }
        }
    }
#undef LDG_TILE
#undef STS_TILE
}

// ---------------- CSR build (parallel 3-phase scan) ----------------
__global__ void csr_count_kernel(const int* __restrict__ ei, int* __restrict__ count) {
    int e = (int)((size_t)blockIdx.x * blockDim.x + threadIdx.x);
    if (e >= N_EDGES) return;
    atomicAdd(&count[ei[N_EDGES + e]], 1);
}

__global__ void csr_scan1_kernel(const int* __restrict__ count,
                                 int* __restrict__ rowstart,
                                 int* __restrict__ blocksum) {
    __shared__ int ts[256];
    const int t = threadIdx.x;
    const int base = blockIdx.x * 1024 + t * 4;
    int c0 = count[base], c1 = count[base + 1], c2 = count[base + 2], c3 = count[base + 3];
    int local = c0 + c1 + c2 + c3;
    ts[t] = local;
    __syncthreads();
#pragma unroll
    for (int off = 1; off < 256; off <<= 1) {
        int v = (t >= off) ? ts[t - off] : 0;
        __syncthreads();
        ts[t] += v;
        __syncthreads();
    }
    int pre = ts[t] - local;
    rowstart[base] = pre;
    rowstart[base + 1] = pre + c0;
    rowstart[base + 2] = pre + c0 + c1;
    rowstart[base + 3] = pre + c0 + c1 + c2;
    if (t == 255) blocksum[blockIdx.x] = ts[255];
}

__global__ void csr_scan2_kernel(int* __restrict__ blocksum) {
    __shared__ int ts[128];
    const int t = threadIdx.x;
    int v0 = blocksum[t];
    ts[t] = v0;
    __syncthreads();
#pragma unroll
    for (int off = 1; off < 128; off <<= 1) {
        int v = (t >= off) ? ts[t - off] : 0;
        __syncthreads();
        ts[t] += v;
        __syncthreads();
    }
    blocksum[t] = ts[t] - v0;
}

__global__ void csr_scan3_kernel(int* __restrict__ rowstart, int* __restrict__ cursor,
                                 const int* __restrict__ blocksum) {
    const int i = blockIdx.x * 1024 + threadIdx.x * 4;
    const int off = blocksum[blockIdx.x];
#pragma unroll
    for (int q = 0; q < 4; q++) {
        int v = rowstart[i + q] + off;
        rowstart[i + q] = v;
        cursor[i + q] = v;
    }
    if (blockIdx.x == 0 && threadIdx.x == 0) rowstart[N_NODES] = N_EDGES;
}

__global__ void csr_fill_kernel(const int* __restrict__ ei, int* __restrict__ cursor,
                                int* __restrict__ csr_src, int* __restrict__ csr_eid) {
    int e = (int)((size_t)blockIdx.x * blockDim.x + threadIdx.x);
    if (e >= N_EDGES) return;
    int d = ei[N_EDGES + e];
    int pos = atomicAdd(&cursor[d], 1);
    csr_src[pos] = ei[e];
    csr_eid[pos] = e;
}

// graph starts from sorted batch
__global__ void gbstart_kernel(const int* __restrict__ batch, int* __restrict__ gb) {
    int n = (int)((size_t)blockIdx.x * blockDim.x + threadIdx.x);
    if (n >= N_NODES) return;
    if (n == 0) {
        for (int gidx = 0; gidx <= batch[0]; gidx++) gb[gidx] = 0;
    } else {
        int b0 = batch[n - 1], b1 = batch[n];
        for (int gidx = b0 + 1; gidx <= b1; gidx++) gb[gidx] = n;
    }
    if (n == N_NODES - 1) {
        for (int gidx = batch[n] + 1; gidx <= N_GRAPHS; gidx++) gb[gidx] = N_NODES;
    }
}

// ---------------- edge gather: agg16[n] = x[n] + sum relu(x[src] + e) ------
__global__ void edge_gather_kernel(const int* __restrict__ rowstart,
                                   const int* __restrict__ csr_src,
                                   const int* __restrict__ csr_eid,
                                   const float* __restrict__ x,
                                   const __half* __restrict__ e,
                                   __half* __restrict__ agg) {
    size_t idx = (size_t)blockIdx.x * blockDim.x + threadIdx.x;
    if (idx >= (size_t)N_NODES * 64) return;
    int n = (int)(idx >> 6);
    int c = (int)(idx & 63);
    int beg = rowstart[n], end = rowstart[n + 1];
    float4 acc = *(const float4*)&x[(size_t)n * D + c * 4];
    for (int k = beg; k < end; k++) {
        int s = csr_src[k];
        int eid = csr_eid[k];
        float4 xv = *(const float4*)&x[(size_t)s * D + c * 4];
        float ev[4];
        ld4h(e + (size_t)eid * D + c * 4, ev);
        acc.x += fmaxf(xv.x + ev[0], 0.f);
        acc.y += fmaxf(xv.y + ev[1], 0.f);
        acc.z += fmaxf(xv.z + ev[2], 0.f);
        acc.w += fmaxf(xv.w + ev[3], 0.f);
    }
    st4h(agg + (size_t)n * D + c * 4, acc);
}

// ---------------- weight transpose ----------------
__global__ void transpose_kernel(const float* __restrict__ in, float* __restrict__ out,
                                 int R, int C) {
    __shared__ float t[32][33];
    int c0 = blockIdx.x * 32, r0 = blockIdx.y * 32;
    for (int i = threadIdx.y; i < 32; i += 8)
        t[i][threadIdx.x] = in[(size_t)(r0 + i) * C + c0 + threadIdx.x];
    __syncthreads();
    for (int i = threadIdx.y; i < 32; i += 8)
        out[(size_t)(c0 + i) * R + r0 + threadIdx.x] = t[threadIdx.x][i];
}

// ---------------- encoders ----------------
__global__ void atom_encode_kernel(const int* __restrict__ xa,
                                   const float* __restrict__ emb,
                                   float* __restrict__ hx0, float* __restrict__ hx1) {
    size_t idx = (size_t)blockIdx.x * blockDim.x + threadIdx.x;
    if (idx >= (size_t)N_NODES * 64) return;
    int n = (int)(idx >> 6);
    int c = (int)(idx & 63);
    float4 acc = make_float4(0.f, 0.f, 0.f, 0.f);
#pragma unroll
    for (int i = 0; i < 9; i++) {
        int t = xa[n * 9 + i];
        const float4 v = *(const float4*)&emb[((size_t)(i * 120 + t)) * D + c * 4];
        acc.x += v.x; acc.y += v.y; acc.z += v.z; acc.w += v.w;
    }
    size_t o = (size_t)n * D + c * 4;
    *(float4*)&hx0[o] = acc;
    *(float4*)&hx1[o] = acc;
}

__global__ void bond_encode_kernel(const int* __restrict__ ea,
                                   const float* __restrict__ emb,
                                   __half* __restrict__ e_out) {
    __shared__ float tab[3 * 6 * D];
    for (int i = threadIdx.x; i < 3 * 6 * D; i += blockDim.x) tab[i] = emb[i];
    __syncthreads();
    size_t total = (size_t)N_EDGES * 64;
    size_t stride = (size_t)gridDim.x * blockDim.x;
    for (size_t idx = (size_t)blockIdx.x * blockDim.x + threadIdx.x; idx < total;
         idx += stride) {
        int n = (int)(idx >> 6);
        int c = (int)(idx & 63);
        float4 acc = make_float4(0.f, 0.f, 0.f, 0.f);
#pragma unroll
        for (int i = 0; i < 3; i++) {
            int t = ea[n * 3 + i];
            const float4 v = *(const float4*)&tab[(i * 6 + t) * D + c * 4];
            acc.x += v.x; acc.y += v.y; acc.z += v.z; acc.w += v.w;
        }
        st4h(e_out + (size_t)n * D + c * 4, acc);
    }
}

// ---------------- GRU / LSTM gates ----------------
__global__ void gru_gate_kernel(const __half* __restrict__ gi,
                                const __half* __restrict__ gh,
                                float* __restrict__ hx) {
    size_t idx = (size_t)blockIdx.x * blockDim.x + threadIdx.x;
    if (idx >= (size_t)N_NODES * 64) return;
    int n = (int)(idx >> 6);
    int c = (int)(idx & 63);
    size_t base = (size_t)n * 3 * D + c * 4;
    float ir[4], iz[4], in_[4], hr[4], hz[4], hn[4];
    ld4h(gi + base, ir); ld4h(gi + base + D, iz); ld4h(gi + base + 2 * D, in_);
    ld4h(gh + base, hr); ld4h(gh + base + D, hz); ld4h(gh + base + 2 * D, hn);
    size_t hidx = (size_t)n * D + c * 4;
    float4 hp = *(const float4*)&hx[hidx];
    float hpv[4] = {hp.x, hp.y, hp.z, hp.w};
    float ov[4];
#pragma unroll
    for (int q = 0; q < 4; q++) {
        float r = sigmoidf_(ir[q] + hr[q]);
        float z = sigmoidf_(iz[q] + hz[q]);
        float nn = tanhf(in_[q] + r * hn[q]);
        ov[q] = (1.0f - z) * nn + z * hpv[q];
    }
    *(float4*)&hx[hidx] = make_float4(ov[0], ov[1], ov[2], ov[3]);
}

__global__ void lstm_gate_kernel(const float* __restrict__ g1,
                                 const float* __restrict__ g2,
                                 float* __restrict__ hs, float* __restrict__ cs) {
    size_t idx = (size_t)blockIdx.x * blockDim.x + threadIdx.x;
    if (idx >= (size_t)N_GRAPHS * D) return;
    int b = (int)(idx >> 8);
    int d = (int)(idx & 255);
    size_t base = (size_t)b * 4 * D + d;
    float ig = sigmoidf_(g1[base] + g2[base]);
    float fg = sigmoidf_(g1[base + D] + g2[base + D]);
    float gg = tanhf(g1[base + 2 * D] + g2[base + 2 * D]);
    float og = sigmoidf_(g1[base + 3 * D] + g2[base + 3 * D]);
    float c = fg * cs[idx] + ig * gg;
    cs[idx] = c;
    hs[idx] = og * tanhf(c);
}

// ---------------- fused Set2Set attention (one block per graph) -----------
// qstar[g] = [hs[g], sum_n softmax(hs[g].x_n) x_n]; batch sorted.
__global__ __launch_bounds__(256) void s2s_attn_kernel(
    const int* __restrict__ gbstart, const float* __restrict__ hs,
    const float* __restrict__ x, float* __restrict__ prod,
    float* __restrict__ qstar) {
    __shared__ float q[D];
    __shared__ float red[8];
    __shared__ float bcast;
    const int gidx = blockIdx.x;
    const int tid = threadIdx.x;
    const int lane = tid & 31;
    const int wid = tid >> 5;
    const int beg = gbstart[gidx], end = gbstart[gidx + 1];

    q[tid] = hs[(size_t)gidx * D + tid];
    __syncthreads();

    // pass 1: dot products (warp per node) + max
    float wmax = -INFINITY;
    for (int n = beg + wid; n < end; n += 8) {
        const float* xv = x + (size_t)n * D;
        float s = 0.f;
#pragma unroll
        for (int j = 0; j < D / 32; j++) s += q[lane + j * 32] * xv[lane + j * 32];
#pragma unroll
        for (int o = 16; o; o >>= 1) s += __shfl_xor_sync(0xFFFFFFFFu, s, o);
        if (lane == 0) prod[n] = s;
        wmax = fmaxf(wmax, s);
    }
#pragma unroll
    for (int o = 16; o; o >>= 1) wmax = fmaxf(wmax, __shfl_xor_sync(0xFFFFFFFFu, wmax, o));
    if (lane == 0) red[wid] = wmax;
    __syncthreads();
    if (tid == 0) {
        float m = red[0];
#pragma unroll
        for (int i = 1; i < 8; i++) m = fmaxf(m, red[i]);
        bcast = m;
    }
    __syncthreads();
    const float m = bcast;

    // pass 2: exp + sum
    float psum = 0.f;
    for (int n = beg + tid; n < end; n += 256) {
        float a = expf(prod[n] - m);
        prod[n] = a;
        psum += a;
    }
#pragma unroll
    for (int o = 16; o; o >>= 1) psum += __shfl_xor_sync(0xFFFFFFFFu, psum, o);
    if (lane == 0) red[wid] = psum;
    __syncthreads();
    if (tid == 0) {
        float s = 0.f;
#pragma unroll
        for (int i = 0; i < 8; i++) s += red[i];
        bcast = s + EPS;
    }
    __syncthreads();
    const float inv_norm = 1.0f / bcast;

    // pass 3: weighted sum over nodes (thread owns dim tid)
    float acc = 0.f;
    for (int n = beg; n < end; n++) {
        float cf = prod[n] * inv_norm;
        acc += cf * x[(size_t)n * D + tid];
    }
    qstar[(size_t)gidx * 2 * D + tid] = q[tid];
    qstar[(size_t)gidx * 2 * D + D + tid] = acc;
}

__global__ void fc_kernel(const float* __restrict__ qstar,
                          const float* __restrict__ fw,
                          const float* __restrict__ fb,
                          float* __restrict__ out) {
    int warp = (int)(((size_t)blockIdx.x * blockDim.x + threadIdx.x) >> 5);
    int lane = threadIdx.x & 31;
    if (warp >= N_GRAPHS) return;
    float s = 0.f;
#pragma unroll
    for (int j = 0; j < (2 * D) / 32; j++)
        s += qstar[(size_t)warp * 2 * D + lane + j * 32] * fw[lane + j * 32];
#pragma unroll
    for (int o = 16; o; o >>= 1) s += __shfl_xor_sync(0xFFFFFFFFu, s, o);
    if (lane == 0) out[warp] = s + fb[0];
}

// ---------------- launch ----------------
extern "C" void kernel_launch(void* const* d_in, const int* in_sizes, int n_in,
                              void* d_out, int out_size) {
    const int* x_atoms = (const int*)d_in[0];
    const int* edge_index = (const int*)d_in[1];
    const int* edge_attr = (const int*)d_in[2];
    const int* batch = (const int*)d_in[3];
    const float* atom_emb = (const float*)d_in[4];
    const float* bond_emb = (const float*)d_in[5];
    const float* gin_w1 = (const float*)d_in[6];
    const float* gin_b1 = (const float*)d_in[7];
    const float* gin_w2 = (const float*)d_in[8];
    const float* gin_b2 = (const float*)d_in[9];
    const float* gru_wih = (const float*)d_in[10];
    const float* gru_whh = (const float*)d_in[11];
    const float* gru_bih = (const float*)d_in[12];
    const float* gru_bhh = (const float*)d_in[13];
    const float* lstm_wih = (const float*)d_in[14];
    const float* lstm_whh = (const float*)d_in[15];
    const float* lstm_bih = (const float*)d_in[16];
    const float* lstm_bhh = (const float*)d_in[17];
    const float* fc_w = (const float*)d_in[18];
    const float* fc_b = (const float*)d_in[19];
    float* out = (float*)d_out;

    float *hx0, *hx1, *g1, *g2, *hs, *cs, *qstar, *prod, *w1t, *w2t;
    __half *e16, *agg16, *t16, *xconv16, *gi16, *gh16;
    int *count, *rowstart, *cursor, *csr_src, *csr_eid, *blocksum, *gbstart;
    cudaGetSymbolAddress((void**)&hx0, g_hx0);
    cudaGetSymbolAddress((void**)&hx1, g_hx1);
    cudaGetSymbolAddress((void**)&e16, g_e16);
    cudaGetSymbolAddress((void**)&agg16, g_agg16);
    cudaGetSymbolAddress((void**)&t16, g_t16);
    cudaGetSymbolAddress((void**)&xconv16, g_xconv16);
    cudaGetSymbolAddress((void**)&gi16, g_gi16);
    cudaGetSymbolAddress((void**)&gh16, g_gh16);
    cudaGetSymbolAddress((void**)&g1, g_g1);
    cudaGetSymbolAddress((void**)&g2, g_g2);
    cudaGetSymbolAddress((void**)&hs, g_hs);
    cudaGetSymbolAddress((void**)&cs, g_cs);
    cudaGetSymbolAddress((void**)&qstar, g_qstar);
    cudaGetSymbolAddress((void**)&prod, g_prod);
    cudaGetSymbolAddress((void**)&w1t, g_w1t);
    cudaGetSymbolAddress((void**)&w2t, g_w2t);
    cudaGetSymbolAddress((void**)&count, g_count);
    cudaGetSymbolAddress((void**)&rowstart, g_rowstart);
    cudaGetSymbolAddress((void**)&cursor, g_cursor);
    cudaGetSymbolAddress((void**)&csr_src, g_csr_src);
    cudaGetSymbolAddress((void**)&csr_eid, g_csr_eid);
    cudaGetSymbolAddress((void**)&blocksum, g_blocksum);
    cudaGetSymbolAddress((void**)&gbstart, g_gbstart);

    cudaFuncSetAttribute(gemm_fullA_kernel<true, true>,
                         cudaFuncAttributeMaxDynamicSharedMemorySize, FK_SMEM);
    cudaFuncSetAttribute(gemm_fullA_kernel<true, false>,
                         cudaFuncAttributeMaxDynamicSharedMemorySize, FK_SMEM);
    cudaFuncSetAttribute(gemm_fullA_kernel<false, false>,
                         cudaFuncAttributeMaxDynamicSharedMemorySize, FK_SMEM);
    cudaFuncSetAttribute(mma_gemm_kernel<false, true, true>,
                         cudaFuncAttributeMaxDynamicSharedMemorySize, GEMM_SMEM);
    cudaFuncSetAttribute(mma_gemm_kernel<false, false, false>,
                         cudaFuncAttributeMaxDynamicSharedMemorySize, GEMM_SMEM);

    const int TPB = 256;

    transpose_kernel<<<dim3(512 / 32, 256 / 32), dim3(32, 8)>>>(gin_w1, w1t, 256, 512);
    transpose_kernel<<<dim3(256 / 32, 512 / 32), dim3(32, 8)>>>(gin_w2, w2t, 512, 256);

    cudaMemsetAsync(count, 0, N_NODES * sizeof(int));
    csr_count_kernel<<<N_EDGES / TPB, TPB>>>(edge_index, count);
    csr_scan1_kernel<<<128, 256>>>(count, rowstart, blocksum);
    csr_scan2_kernel<<<1, 128>>>(blocksum);
    csr_scan3_kernel<<<128, 256>>>(rowstart, cursor, blocksum);
    csr_fill_kernel<<<N_EDGES / TPB, TPB>>>(edge_index, cursor, csr_src, csr_eid);
    gbstart_kernel<<<N_NODES / TPB, TPB>>>(batch, gbstart);

    atom_encode_kernel<<<(N_NODES * 64) / TPB, TPB>>>(x_atoms, atom_emb, hx0, hx1);
    bond_encode_kernel<<<2048, TPB>>>(edge_attr, bond_emb, e16);
    cudaMemsetAsync(hs, 0, (size_t)N_GRAPHS * D * sizeof(float));
    cudaMemsetAsync(cs, 0, (size_t)N_GRAPHS * D * sizeof(float));
    cudaMemsetAsync(qstar, 0, (size_t)N_GRAPHS * 2 * D * sizeof(float));

    const dim3 fkgrid(1, N_NODES / 128);
    for (int layer = 0; layer < 3; layer++) {
        edge_gather_kernel<<<(N_NODES * 64) / TPB, TPB>>>(rowstart, csr_src, csr_eid,
                                                          hx1, e16, agg16);
        gemm_fullA_kernel<true, true><<<fkgrid, 512, FK_SMEM>>>(
            agg16, w1t, gin_b1, t16, 512);
        mma_gemm_kernel<false, true, true>
            <<<dim3(1, N_NODES / 128), GEMM_TPB, GEMM_SMEM>>>(
                t16, w2t, gin_b2, xconv16, N_NODES, 256, 512);
        gemm_fullA_kernel<true, false><<<fkgrid, 512, FK_SMEM>>>(
            xconv16, gru_wih, gru_bih, gi16, 768);
        gemm_fullA_kernel<false, false><<<fkgrid, 512, FK_SMEM>>>(
            hx0, gru_whh, gru_bhh, gh16, 768);
        gru_gate_kernel<<<(N_NODES * 64) / TPB, TPB>>>(gi16, gh16, hx0);
        gemm_fullA_kernel<false, false><<<fkgrid, 512, FK_SMEM>>>(
            hx0, gru_wih + 768 * 256, gru_bih + 768, gi16, 768);
        gemm_fullA_kernel<false, false><<<fkgrid, 512, FK_SMEM>>>(
            hx1, gru_whh + 768 * 256, gru_bhh + 768, gh16, 768);
        gru_gate_kernel<<<(N_NODES * 64) / TPB, TPB>>>(gi16, gh16, hx1);
    }

    for (int step = 0; step < 3; step++) {
        mma_gemm_kernel<false, false, false>
            <<<dim3(1024 / 256, N_GRAPHS / 128), GEMM_TPB, GEMM_SMEM>>>(
                qstar, lstm_wih, lstm_bih, g1, N_GRAPHS, 1024, 512);
        mma_gemm_kernel<false, false, false>
            <<<dim3(1024 / 256, N_GRAPHS / 128), GEMM_TPB, GEMM_SMEM>>>(
                hs, lstm_whh, lstm_bhh, g2, N_GRAPHS, 1024, 256);
        lstm_gate_kernel<<<(N_GRAPHS * D) / TPB, TPB>>>(g1, g2, hs, cs);
        s2s_attn_kernel<<<N_GRAPHS, 256>>>(gbstart, hs, hx1, prod, qstar);
    }

    fc_kernel<<<(N_GRAPHS * 32) / TPB, TPB>>>(qstar, fc_w, fc_b, out);
}